// round 16
// baseline (speedup 1.0000x reference)
#include <cuda_runtime.h>
#include <cuda_bf16.h>
#include <math.h>

// ---------------------------------------------------------------------------
// Problem constants
// ---------------------------------------------------------------------------
#define BATCH   2
#define SEQ     2048
#define DIM     1024
#define HEADS   16
#define DHEAD   64
#define DEPTH   2
#define DCOND   4096
#define DFF     2730
#define TOK     (BATCH*SEQ)
#define SOFTCAP 50.0f
#define QK_SCALE 0.125f
#define TWO_PI  6.2831853071795864769f
#define MASKVAL (-1.0e4f)

#define FOURIER_LD 1032       // 1025 padded to multiple of 8
#define ACT_LD     2736       // 2730 padded to multiple of 8

// tcgen05 only exists in arch-specific (sm_103a) device passes.
#if defined(__CUDA_ARCH_FEAT_SM103_ALL) || \
    (defined(__CUDA_ARCH_SPECIFIC__) && (__CUDA_ARCH_SPECIFIC__ == 1030))
#define HAS_TC5 1
#else
#define HAS_TC5 0
#endif

// Merged cond-GEMM epilogue pointers (act == 7)
struct MergedEp {
    const float* bf0; const float* ba0; const float* bf1; const float* ba1;
    float* gb0; float* gt0; float* gb1; float* gt1;
};

// ---------------------------------------------------------------------------
// Scratch (static device globals; no allocation allowed; zero-initialized)
// ---------------------------------------------------------------------------
__device__ float g_gba   [(size_t)TOK * 2 * DIM];
__device__ float g_gbf   [(size_t)TOK * 2 * DIM];
__device__ float g_gatea [(size_t)TOK * DIM];
__device__ float g_gatef [(size_t)TOK * DIM];
__device__ float g_x     [(size_t)TOK * DIM];

__device__ __nv_bfloat16 g_fh   [(size_t)TOK * FOURIER_LD];
__device__ __nv_bfloat16 g_fl   [(size_t)TOK * FOURIER_LD];
__device__ __nv_bfloat16 g_condh[(size_t)TOK * DCOND];
__device__ __nv_bfloat16 g_condl[(size_t)TOK * DCOND];
__device__ __nv_bfloat16 g_hh   [(size_t)TOK * DIM];
__device__ __nv_bfloat16 g_hl   [(size_t)TOK * DIM];
__device__ __nv_bfloat16 g_qkvh [(size_t)TOK * 3 * DIM];
__device__ __nv_bfloat16 g_qkvl [(size_t)TOK * 3 * DIM];
__device__ __nv_bfloat16 g_oh   [(size_t)TOK * DIM];
__device__ __nv_bfloat16 g_ol   [(size_t)TOK * DIM];
__device__ __nv_bfloat16 g_acth [(size_t)TOK * ACT_LD];   // pad cols stay 0
__device__ __nv_bfloat16 g_actl [(size_t)TOK * ACT_LD];

// all weights, split TRANSPOSED ([N,Kpad], K-major) once per launch
__device__ __nv_bfloat16 g_wh[80000000];
__device__ __nv_bfloat16 g_wl[80000000];

// ---------------------------------------------------------------------------
// Primitives
// ---------------------------------------------------------------------------
__device__ __forceinline__ void split_bf16(float x, __nv_bfloat16& h, __nv_bfloat16& l) {
    h = __float2bfloat16(x);
    l = __float2bfloat16(x - __bfloat162float(h));
}
__device__ __forceinline__ unsigned pk2(__nv_bfloat16 a, __nv_bfloat16 b) {
    unsigned short ua = __bfloat16_as_ushort(a), ub = __bfloat16_as_ushort(b);
    return ((unsigned)ub << 16) | (unsigned)ua;
}
__device__ __forceinline__ unsigned smaddr(const void* p) {
    return (unsigned)__cvta_generic_to_shared(p);
}
__device__ __forceinline__ void ldsm4(unsigned r[4], unsigned addr) {
    asm volatile("ldmatrix.sync.aligned.m8n8.x4.shared.b16 {%0,%1,%2,%3}, [%4];"
                 : "=r"(r[0]), "=r"(r[1]), "=r"(r[2]), "=r"(r[3]) : "r"(addr));
}
__device__ __forceinline__ void ldsm4t(unsigned r[4], unsigned addr) {
    asm volatile("ldmatrix.sync.aligned.m8n8.x4.trans.shared.b16 {%0,%1,%2,%3}, [%4];"
                 : "=r"(r[0]), "=r"(r[1]), "=r"(r[2]), "=r"(r[3]) : "r"(addr));
}
__device__ __forceinline__ void mma16(float acc[4], const unsigned a[4], const unsigned b[2]) {
    asm volatile(
        "mma.sync.aligned.m16n8k16.row.col.f32.bf16.bf16.f32 "
        "{%0,%1,%2,%3},{%4,%5,%6,%7},{%8,%9},{%0,%1,%2,%3};"
        : "+f"(acc[0]), "+f"(acc[1]), "+f"(acc[2]), "+f"(acc[3])
        : "r"(a[0]), "r"(a[1]), "r"(a[2]), "r"(a[3]), "r"(b[0]), "r"(b[1]));
}
#define CP_ASYNC16(dst, src, bytes) \
    asm volatile("cp.async.cg.shared.global [%0], [%1], 16, %2;" :: \
                 "r"(dst), "l"(src), "r"(bytes))
#define CP_COMMIT()  asm volatile("cp.async.commit_group;")
#define CP_WAIT0()   asm volatile("cp.async.wait_group 0;")
#define CP_WAIT1()   asm volatile("cp.async.wait_group 1;")

__device__ __forceinline__ void mbar_init(unsigned addr, unsigned cnt) {
    asm volatile("mbarrier.init.shared.b64 [%0], %1;" :: "r"(addr), "r"(cnt) : "memory");
}
__device__ __forceinline__ void mbar_wait(unsigned addr, unsigned parity) {
    asm volatile(
        "{\n\t.reg .pred P;\n\t"
        "W_%=:\n\t"
        "mbarrier.try_wait.parity.acquire.cta.shared::cta.b64 P, [%0], %1, 0x989680;\n\t"
        "@P bra D_%=;\n\t"
        "bra W_%=;\n\t"
        "D_%=:\n\t}"
        :: "r"(addr), "r"(parity) : "memory");
}
#define FENCE_PROXY() asm volatile("fence.proxy.async.shared::cta;" ::: "memory")

#if HAS_TC5
// ---- tcgen05 primitives (cg1), only compiled in arch-specific pass ----
__device__ __forceinline__ unsigned long long mkdesc(unsigned a) {
    // SW128, version=1 (Blackwell), SBO=64, LBO=1, K-major
    const unsigned long long B =
        (2ULL << 61) | (1ULL << 46) | (64ULL << 32) | (1ULL << 16);
    return B | (unsigned long long)((a >> 4) & 0x3FFF);
}
// idesc kind::f16: f32 accum, bf16 a/b, M=128, N=128
#define TC5_IDESC 0x8200490u

__device__ __forceinline__ void tc5_mma(unsigned d, unsigned long long ad,
                                        unsigned long long bd, unsigned en) {
    asm volatile(
        "{\n\t.reg .pred p;\n\t"
        "setp.ne.u32 p, %4, 0;\n\t"
        "tcgen05.mma.cta_group::1.kind::f16 [%0], %1, %2, %3, {%5,%5,%5,%5}, p;\n\t"
        "}"
        :: "r"(d), "l"(ad), "l"(bd), "r"(TC5_IDESC), "r"(en), "r"(0u)
        : "memory");
}
__device__ __forceinline__ void tc5_commit(unsigned mbar) {
    asm volatile(
        "tcgen05.commit.cta_group::1.mbarrier::arrive::one.shared::cluster.b64 [%0];"
        :: "r"(mbar) : "memory");
}
#define TC5_FENCE_AFTER() asm volatile("tcgen05.fence::after_thread_sync;" ::: "memory")
#define TC5_WAIT_LD() asm volatile("tcgen05.wait::ld.sync.aligned;" ::: "memory")

__device__ __forceinline__ void ldtm_x32(unsigned* r, unsigned addr) {
    asm volatile(
        "tcgen05.ld.sync.aligned.32x32b.x32.b32 "
        "{%0,%1,%2,%3,%4,%5,%6,%7,"
        "%8,%9,%10,%11,%12,%13,%14,%15,"
        "%16,%17,%18,%19,%20,%21,%22,%23,"
        "%24,%25,%26,%27,%28,%29,%30,%31}, [%32];"
        : "=r"(r[0]),  "=r"(r[1]),  "=r"(r[2]),  "=r"(r[3]),
          "=r"(r[4]),  "=r"(r[5]),  "=r"(r[6]),  "=r"(r[7]),
          "=r"(r[8]),  "=r"(r[9]),  "=r"(r[10]), "=r"(r[11]),
          "=r"(r[12]), "=r"(r[13]), "=r"(r[14]), "=r"(r[15]),
          "=r"(r[16]), "=r"(r[17]), "=r"(r[18]), "=r"(r[19]),
          "=r"(r[20]), "=r"(r[21]), "=r"(r[22]), "=r"(r[23]),
          "=r"(r[24]), "=r"(r[25]), "=r"(r[26]), "=r"(r[27]),
          "=r"(r[28]), "=r"(r[29]), "=r"(r[30]), "=r"(r[31])
        : "r"(addr));
}
#endif // HAS_TC5

#define SWZ(o) ((o) ^ (((o) >> 3) & 0x70))

__device__ __forceinline__ float softcap_tanh(float S) {
    float x = S * (1.0f / SOFTCAP);
    float u = x * x;
    if (u <= 0.25f) {
        float p = -0.33333333f + u * (0.13333333f + u * (-0.05396825f +
                  u * (0.02186949f - u * 0.00886322f)));
        return S * (1.0f + u * p);
    } else {
        float ax = fminf(fabsf(x), 20.f);
        float t = __expf(-2.f * ax);
        float r = __fdividef(1.f - t, 1.f + t);
        return copysignf(r, x) * SOFTCAP;
    }
}

__device__ __forceinline__ float block_reduce_sum(float v, float* sm) {
    int lane = threadIdx.x & 31, warp = threadIdx.x >> 5;
#pragma unroll
    for (int o = 16; o; o >>= 1) v += __shfl_xor_sync(0xffffffffu, v, o);
    if (lane == 0) sm[warp] = v;
    __syncthreads();
    if (warp == 0) {
        v = (lane < 8) ? sm[lane] : 0.f;
#pragma unroll
        for (int o = 4; o; o >>= 1) v += __shfl_xor_sync(0xffffffffu, v, o);
        if (lane == 0) sm[0] = v;
    }
    __syncthreads();
    float r = sm[0];
    __syncthreads();
    return r;
}

// ---------------------------------------------------------------------------
// Weight split + transpose: src f32 [R,C] -> dh/dl bf16 [rowmap(C), Rpad]
// pmode 0: rowmap = identity.  pmode 1 (GEGLU interleave): src col c<pd ->
// dst row 2c, src col c>=pd -> dst row 2(c-pd)+1.
// ---------------------------------------------------------------------------
__global__ void wsplitT_kernel(const float* __restrict__ src,
                               __nv_bfloat16* __restrict__ dh,
                               __nv_bfloat16* __restrict__ dl,
                               int R, int C, int Rpad, int pmode, int pd)
{
    __shared__ float ts[64][65];
    int t = threadIdx.x;
    int c0 = blockIdx.x * 64, r0 = blockIdx.y * 64;
#pragma unroll
    for (int i = 0; i < 4; i++) {
        int q = i * 256 + t;
        int r = q >> 4, c4 = (q & 15) * 4;
        int sr = r0 + r, sc = c0 + c4;
        float4 v = make_float4(0.f, 0.f, 0.f, 0.f);
        if (sr < R && sc < C)
            v = *(const float4*)(src + (size_t)sr * C + sc);
        ts[r][c4 + 0] = v.x; ts[r][c4 + 1] = v.y;
        ts[r][c4 + 2] = v.z; ts[r][c4 + 3] = v.w;
    }
    __syncthreads();
#pragma unroll
    for (int i = 0; i < 4; i++) {
        int q = i * 256 + t;
        int c = q >> 4, rq = (q & 15) * 4;
        int dc = c0 + c, dr = r0 + rq;
        if (dc < C && dr < Rpad) {
            int drow = dc;
            if (pmode == 1) drow = (dc < pd) ? 2 * dc : 2 * (dc - pd) + 1;
            __nv_bfloat16 h[4], l[4];
#pragma unroll
            for (int e = 0; e < 4; e++) split_bf16(ts[rq + e][c], h[e], l[e]);
            *(uint2*)&dh[(size_t)drow * Rpad + dr] =
                make_uint2(pk2(h[0], h[1]), pk2(h[2], h[3]));
            *(uint2*)&dl[(size_t)drow * Rpad + dr] =
                make_uint2(pk2(l[0], l[1]), pk2(l[2], l[3]));
        }
    }
}

// ---------------------------------------------------------------------------
// GEMM: C[M,N] = epilogue(A[M,K] @ WT[N,K]^T [+bias])
// Arch-specific pass: tcgen05 SS, CTA tile 128x256, BK=64, 3-term bf16 split.
// act: 0 plain f32, 1 +bias f32, 4 gated residual (C=g_x+=),
//      5 +bias silu -> split bf16 out, 6 +bias gated residual,
//      7 merged cond epilogue (MergedEp),
//      8 qkv: rotary(q,k)+scale(q) -> split bf16 (bias = rot table),
//      9 ff1 interleaved: bias+GEGLU -> split bf16 act planes (bias = ff_b1)
// ---------------------------------------------------------------------------
__global__ __launch_bounds__(256, 1)
void gemm_tc5_kernel(
    const __nv_bfloat16* __restrict__ Ah, const __nv_bfloat16* __restrict__ Al, int lda,
    const __nv_bfloat16* __restrict__ Bh, const __nv_bfloat16* __restrict__ Bl, int ldb,
    const float* __restrict__ bias,
    float* __restrict__ C, int ldc,
    __nv_bfloat16* __restrict__ Csh, __nv_bfloat16* __restrict__ Csl,
    int M, int N, int K, int act,
    const int* __restrict__ skmp,
    const float* __restrict__ gate, const float* __restrict__ ls,
    const int* __restrict__ mp, MergedEp mep)
{
    const int row0 = blockIdx.y * 128, col0 = blockIdx.x * 256;
    if (skmp) {
        int bb = row0 >> 11;
        int n0 = row0 & (SEQ - 1);
        int o0 = skmp[bb*6+1], L0 = skmp[bb*6+2];
        int o1 = skmp[bb*6+4], L1 = skmp[bb*6+5];
        bool hit = (n0 + 127 >= o0 && n0 < o0 + L0) ||
                   (n0 + 127 >= o1 && n0 < o1 + L1);
        if (!hit) return;
    }

    const int tid = threadIdx.x;
    const int wid = tid >> 5, lane = tid & 31;

#if HAS_TC5
    // ===================== tcgen05 path (128x256) =====================
    extern __shared__ __align__(16) char dsm_raw[];
    char* dsm = (char*)(((unsigned long long)dsm_raw + 1023) & ~1023ULL);
    auto planeA = [&](int s, int p) -> char* { return dsm + s * 98304 + p * 16384; };
    auto planeB = [&](int s, int p) -> char* { return dsm + s * 98304 + 32768 + p * 32768; };

    __shared__ unsigned sh_tmem[1];
    __shared__ __align__(8) unsigned long long sh_mbar[2];

    if (wid == 0)
        asm volatile("tcgen05.alloc.cta_group::1.sync.aligned.shared::cta.b32 [%0], %1;"
                     :: "r"(smaddr(sh_tmem)), "r"(512u) : "memory");
    if (tid == 0) { mbar_init(smaddr(&sh_mbar[0]), 1); mbar_init(smaddr(&sh_mbar[1]), 1); }
    __syncthreads();
    unsigned tmem_base;
    asm volatile("ld.shared.b32 %0, [%1];" : "=r"(tmem_base) : "r"(smaddr(sh_tmem)));

    const int nk = (K + 63) >> 6;

    auto load_stage = [&](int k0, int s) {
        unsigned baseA_h = smaddr(planeA(s, 0));
        unsigned baseA_l = smaddr(planeA(s, 1));
        unsigned baseB_h = smaddr(planeB(s, 0));
        unsigned baseB_l = smaddr(planeB(s, 1));
#pragma unroll
        for (int i = 0; i < 4; i++) {
            int q = tid + i * 256;
            int r = q >> 3;
            int cb = (q & 7) * 16;
            unsigned sw = SWZ(r * 128 + cb);
            int kg = k0 + (cb >> 1);
            int abytes = (kg < lda) ? 16 : 0;
            const __nv_bfloat16* pah = abytes ? Ah + (size_t)(row0 + r) * lda + kg : Ah;
            const __nv_bfloat16* pal = abytes ? Al + (size_t)(row0 + r) * lda + kg : Al;
            CP_ASYNC16(baseA_h + sw, pah, abytes);
            CP_ASYNC16(baseA_l + sw, pal, abytes);
        }
#pragma unroll
        for (int i = 0; i < 8; i++) {
            int q = tid + i * 256;
            int r = q >> 3;
            int cb = (q & 7) * 16;
            unsigned sw = SWZ(r * 128 + cb);
            int kg = k0 + (cb >> 1);
            int bbytes = ((col0 + r) < N && kg < ldb) ? 16 : 0;
            const __nv_bfloat16* pbh = bbytes ? Bh + (size_t)(col0 + r) * ldb + kg : Bh;
            const __nv_bfloat16* pbl = bbytes ? Bl + (size_t)(col0 + r) * ldb + kg : Bl;
            CP_ASYNC16(baseB_h + sw, pbh, bbytes);
            CP_ASYNC16(baseB_l + sw, pbl, bbytes);
        }
        CP_COMMIT();
    };

    int phs[2] = {0, 0};
    load_stage(0, 0);

    for (int t = 0; t < nk; t++) {
        int b = t & 1;
        if (t + 1 < nk) {
            int nb = b ^ 1;
            if (t >= 1) { mbar_wait(smaddr(&sh_mbar[nb]), phs[nb]); phs[nb] ^= 1; }
            load_stage((t + 1) * 64, nb);
            CP_WAIT1();
        } else {
            CP_WAIT0();
        }
        FENCE_PROXY();
        __syncthreads();

        if (tid == 0) {
            unsigned long long dAh = mkdesc(smaddr(planeA(b, 0)));
            unsigned long long dAl = mkdesc(smaddr(planeA(b, 1)));
            unsigned long long dBh = mkdesc(smaddr(planeB(b, 0)));
            unsigned long long dBl = mkdesc(smaddr(planeB(b, 1)));
#pragma unroll
            for (int nh = 0; nh < 2; nh++) {
                unsigned d = tmem_base + nh * 128;
                unsigned long long bh = dBh + nh * 1024;
                unsigned long long bl = dBl + nh * 1024;
#pragma unroll
                for (int ks = 0; ks < 4; ks++) {
                    unsigned long long oa = ks * 2;
                    unsigned en0 = (t == 0 && ks == 0) ? 0u : 1u;
                    tc5_mma(d, dAh + oa, bh + oa, en0);
                    tc5_mma(d, dAh + oa, bl + oa, 1u);
                    tc5_mma(d, dAl + oa, bh + oa, 1u);
                }
            }
            tc5_commit(smaddr(&sh_mbar[b]));
        }
    }

    {
        int lb = (nk - 1) & 1;
        mbar_wait(smaddr(&sh_mbar[lb]), phs[lb]);
    }
    TC5_FENCE_AFTER();

    {
        int cb0 = (wid >> 2) * 64;
        int rr = row0 + (wid & 3) * 32 + lane;
        bool mod = false;
        if (act == 4 || act == 6) {
            int bb = rr >> 11, nn = rr & (SEQ - 1);
            int o0 = mp[bb*6+1], e0 = o0 + mp[bb*6+2];
            int o1 = mp[bb*6+4], e1 = o1 + mp[bb*6+5];
            mod = (nn >= o0 && nn < e0) || (nn >= o1 && nn < e1);
        }
        int nrow = rr & (SEQ - 1);
#pragma unroll
        for (int nh = 0; nh < 2; nh++) {
            unsigned dreg[64];
            ldtm_x32(dreg,      tmem_base + nh * 128 + cb0);
            ldtm_x32(dreg + 32, tmem_base + nh * 128 + cb0 + 32);
            TC5_WAIT_LD();

            if (act == 8) {
                // qkv: rotary on q,k, scale q, split -> Csh/Csl (ld 3072)
#pragma unroll 2
                for (int j = 0; j < 64; j += 2) {
                    int cc = col0 + nh * 128 + cb0 + j;
                    float e = __uint_as_float(dreg[j]);
                    float o = __uint_as_float(dreg[j + 1]);
                    int which = cc >> 10;
                    if (which < 2) {
                        int pr = (cc & 63) >> 1;
                        float th = bias[nrow * 64 + pr * 2];
                        float cs = cosf(th), sn = sinf(th);
                        float ne = e * cs - o * sn;
                        float no = o * cs + e * sn;
                        if (which == 0) { ne *= QK_SCALE; no *= QK_SCALE; }
                        e = ne; o = no;
                    }
                    long long idx = (long long)rr * 3072 + cc;
                    __nv_bfloat16 hh, ll;
                    split_bf16(e, hh, ll);
                    Csh[idx] = hh; Csl[idx] = ll;
                    split_bf16(o, hh, ll);
                    Csh[idx + 1] = hh; Csl[idx + 1] = ll;
                }
            } else if (act == 9) {
                // ff1 interleaved [u0,g0,u1,g1,...]: bias + GEGLU -> act planes
#pragma unroll 2
                for (int j = 0; j < 64; j += 2) {
                    int cc = col0 + nh * 128 + cb0 + j;
                    if (cc >= N) break;
                    int c = cc >> 1;
                    float u = __uint_as_float(dreg[j]) + bias[c];
                    float g = __uint_as_float(dreg[j + 1]) + bias[DFF + c];
                    float ge = 0.5f * g * (1.f + erff(g * 0.70710678118654752f));
                    float v = ge * u;
                    long long idx = (long long)rr * ACT_LD + c;
                    __nv_bfloat16 hh, ll;
                    split_bf16(v, hh, ll);
                    Csh[idx] = hh; Csl[idx] = ll;
                }
            } else {
#pragma unroll 4
                for (int j = 0; j < 64; j++) {
                    int cc = col0 + nh * 128 + cb0 + j;
                    if (cc >= N) break;
                    float v = __uint_as_float(dreg[j]);
                    long long idx = (long long)rr * ldc + cc;
                    if (act == 0) {
                        C[idx] = v;
                    } else if (act == 1) {
                        C[idx] = v + bias[cc];
                    } else if (act == 5) {
                        float s = v + bias[cc];
                        s = s / (1.f + __expf(-s));
                        __nv_bfloat16 hh, ll;
                        split_bf16(s, hh, ll);
                        Csh[idx] = hh; Csl[idx] = ll;
                    } else if (act == 7) {
                        if (cc < 2048) {
                            mep.gb0[(long long)rr * 2048 + cc] = v + mep.bf0[cc];
                        } else if (cc < 3072) {
                            int c2 = cc - 2048;
                            mep.gt0[(long long)rr * 1024 + c2] =
                                1.f / (1.f + __expf(-(v + mep.ba0[c2])));
                        } else if (cc < 5120) {
                            int c2 = cc - 3072;
                            mep.gb1[(long long)rr * 2048 + c2] = v + mep.bf1[c2];
                        } else {
                            int c2 = cc - 5120;
                            mep.gt1[(long long)rr * 1024 + c2] =
                                1.f / (1.f + __expf(-(v + mep.ba1[c2])));
                        }
                    } else { // 4 or 6: gated residual into C (=g_x)
                        if (act == 6) v += bias[cc];
                        float rterm = mod ? v * gate[(long long)rr * N + cc]
                                          : v * (ls[cc] + 1.f);
                        C[idx] += rterm;
                    }
                }
            }
        }
    }

    __syncthreads();
    if (wid == 0)
        asm volatile("tcgen05.dealloc.cta_group::1.sync.aligned.b32 %0, %1;"
                     :: "r"(tmem_base), "r"(512u));

#else
    // ===================== mma.sync fallback (NT, two 128-col halves) ========
    __shared__ __align__(16) __nv_bfloat16 As[2][128][40];
    __shared__ __align__(16) __nv_bfloat16 Bs2[2][128][40];

    const int wr = wid & 3, wc = wid >> 2;
    const int lr = tid >> 1, lq = (tid & 1) * 8;

    for (int nh = 0; nh < 2; nh++) {
        int col0h = col0 + nh * 128;
        if (col0h >= N) break;

        auto load_stage = [&](int k0, int s) {
            int kg = k0 + lq;
            int abytes = (kg < lda) ? 16 : 0;
            const __nv_bfloat16* pah = abytes ? Ah + (size_t)(row0 + lr) * lda + kg : Ah;
            const __nv_bfloat16* pal = abytes ? Al + (size_t)(row0 + lr) * lda + kg : Al;
            CP_ASYNC16(smaddr(&As[s][lr][lq]),      pah, abytes);
            CP_ASYNC16(smaddr(&As[s][lr][16 + lq]), pal, abytes);
            int bbytes = ((col0h + lr) < N && kg < ldb) ? 16 : 0;
            const __nv_bfloat16* pbh = bbytes ? Bh + (size_t)(col0h + lr) * ldb + kg : Bh;
            const __nv_bfloat16* pbl = bbytes ? Bl + (size_t)(col0h + lr) * ldb + kg : Bl;
            CP_ASYNC16(smaddr(&Bs2[s][lr][lq]),      pbh, bbytes);
            CP_ASYNC16(smaddr(&Bs2[s][lr][16 + lq]), pbl, bbytes);
            CP_COMMIT();
        };

        float acc[2][8][4] = {};
        const int nk = (K + 15) >> 4;

        load_stage(0, 0);

        for (int t = 0; t < nk; t++) {
            int buf = t & 1;
            if (t + 1 < nk) { load_stage((t + 1) * 16, buf ^ 1); CP_WAIT1(); }
            else            { CP_WAIT0(); }
            __syncthreads();

            unsigned ah[2][4], al[2][4], bh[8][2], bl[8][2];
#pragma unroll
            for (int mt = 0; mt < 2; mt++) {
                int row = wr * 32 + mt * 16 + (lane & 15);
                int kk = (lane >> 4) * 8;
                ldsm4(ah[mt], smaddr(&As[buf][row][kk]));
                ldsm4(al[mt], smaddr(&As[buf][row][16 + kk]));
            }
#pragma unroll
            for (int ntp = 0; ntp < 4; ntp++) {
                int row = wc * 64 + ntp * 16 + (lane & 7) + ((lane >> 4) & 1) * 8;
                int col = ((lane >> 3) & 1) * 8;
                unsigned r4[4];
                ldsm4(r4, smaddr(&Bs2[buf][row][col]));
                bh[2*ntp][0] = r4[0]; bh[2*ntp][1] = r4[1];
                bh[2*ntp+1][0] = r4[2]; bh[2*ntp+1][1] = r4[3];
                ldsm4(r4, smaddr(&Bs2[buf][row][16 + col]));
                bl[2*ntp][0] = r4[0]; bl[2*ntp][1] = r4[1];
                bl[2*ntp+1][0] = r4[2]; bl[2*ntp+1][1] = r4[3];
            }
#pragma unroll
            for (int mt = 0; mt < 2; mt++)
#pragma unroll
                for (int nt = 0; nt < 8; nt++) {
                    mma16(acc[mt][nt], ah[mt], bh[nt]);
                    mma16(acc[mt][nt], ah[mt], bl[nt]);
                    mma16(acc[mt][nt], al[mt], bh[nt]);
                }
            __syncthreads();
        }

#pragma unroll
        for (int mt = 0; mt < 2; mt++) {
            int r = row0 + wr * 32 + mt * 16 + (lane >> 2);
#pragma unroll
            for (int nt = 0; nt < 8; nt++) {
                int c = col0h + wc * 64 + nt * 8 + ((lane & 3) << 1);
#pragma unroll
                for (int ep = 0; ep < 2; ep++) {   // element pair: rows r, r+8
                    int rr = r + ep * 8;
                    int cc = c;
                    if (rr >= M || cc >= N) continue;
                    float v0 = acc[mt][nt][ep * 2 + 0];
                    float v1 = acc[mt][nt][ep * 2 + 1];
                    if (act == 8) {
                        int which = cc >> 10;
                        if (which < 2) {
                            int nrow = rr & (SEQ - 1);
                            int pr = (cc & 63) >> 1;
                            float th = bias[nrow * 64 + pr * 2];
                            float cs = cosf(th), sn = sinf(th);
                            float ne = v0 * cs - v1 * sn;
                            float no = v1 * cs + v0 * sn;
                            if (which == 0) { ne *= QK_SCALE; no *= QK_SCALE; }
                            v0 = ne; v1 = no;
                        }
                        long long idx = (long long)rr * 3072 + cc;
                        __nv_bfloat16 hh, ll;
                        split_bf16(v0, hh, ll); Csh[idx] = hh; Csl[idx] = ll;
                        split_bf16(v1, hh, ll); Csh[idx+1] = hh; Csl[idx+1] = ll;
                    } else if (act == 9) {
                        int cf = cc >> 1;
                        float u = v0 + bias[cf];
                        float g = v1 + bias[DFF + cf];
                        float ge = 0.5f * g * (1.f + erff(g * 0.70710678118654752f));
                        float vv = ge * u;
                        long long idx = (long long)rr * ACT_LD + cf;
                        __nv_bfloat16 hh, ll;
                        split_bf16(vv, hh, ll); Csh[idx] = hh; Csl[idx] = ll;
                    } else {
#pragma unroll
                        for (int e2 = 0; e2 < 2; e2++) {
                            int c2 = cc + e2;
                            if (c2 >= N) continue;
                            float v = (e2 == 0) ? v0 : v1;
                            long long idx = (long long)rr * ldc + c2;
                            if (act == 0) {
                                C[idx] = v;
                            } else if (act == 1) {
                                C[idx] = v + bias[c2];
                            } else if (act == 5) {
                                float s = v + bias[c2];
                                s = s / (1.f + __expf(-s));
                                __nv_bfloat16 hh, ll;
                                split_bf16(s, hh, ll);
                                Csh[idx] = hh; Csl[idx] = ll;
                            } else if (act == 7) {
                                if (c2 < 2048) {
                                    mep.gb0[(long long)rr * 2048 + c2] = v + mep.bf0[c2];
                                } else if (c2 < 3072) {
                                    int c3 = c2 - 2048;
                                    mep.gt0[(long long)rr * 1024 + c3] =
                                        1.f / (1.f + __expf(-(v + mep.ba0[c3])));
                                } else if (c2 < 5120) {
                                    int c3 = c2 - 3072;
                                    mep.gb1[(long long)rr * 2048 + c3] = v + mep.bf1[c3];
                                } else {
                                    int c3 = c2 - 5120;
                                    mep.gt1[(long long)rr * 1024 + c3] =
                                        1.f / (1.f + __expf(-(v + mep.ba1[c3])));
                                }
                            } else {
                                if (act == 6) v += bias[c2];
                                int bb = rr >> 11, nn = rr & (SEQ - 1);
                                int o0 = mp[bb*6+1], e0 = o0 + mp[bb*6+2];
                                int o1 = mp[bb*6+4], e1 = o1 + mp[bb*6+5];
                                bool mod = (nn >= o0 && nn < e0) || (nn >= o1 && nn < e1);
                                float rterm = mod ? v * gate[(long long)rr * N + c2]
                                                  : v * (ls[c2] + 1.f);
                                C[idx] += rterm;
                            }
                        }
                    }
                }
            }
        }
        __syncthreads();
    }
#endif
}

// ---------------------------------------------------------------------------
// Flash attention on pre-split qkv planes (mma.sync; ~5% of MACs).
// ---------------------------------------------------------------------------
__global__ __launch_bounds__(256, 1)
void flash_kernel(const int* __restrict__ mp)
{
    __shared__ __align__(16) __nv_bfloat16 K2[64][136];
    __shared__ __align__(16) __nv_bfloat16 V2[64][136];

    const int tid = threadIdx.x;
    const int lane = tid & 31, w = tid >> 5;
    const int z = blockIdx.y, b = z >> 4, h = z & 15;
    const int i0 = blockIdx.x * 128;

    const __nv_bfloat16* qh_p = g_qkvh + (long long)b * SEQ * 3072 + h * 64;
    const __nv_bfloat16* ql_p = g_qkvl + (long long)b * SEQ * 3072 + h * 64;

    const int off0 = mp[b*6+1], end0 = off0 + mp[b*6+2];
    const int off1 = mp[b*6+4], end1 = off1 + mp[b*6+5];

    unsigned qh[4][4], ql[4][4];
#pragma unroll
    for (int half = 0; half < 2; half++) {
#pragma unroll
        for (int p = 0; p < 2; p++) {
            int f = p * 256 + tid;
            int r = f >> 3, s = (f & 7) * 8;
            long long rowoff = (long long)(i0 + half * 64 + r) * 3072 + s;
            *(uint4*)&K2[r][s]      = *(const uint4*)(qh_p + rowoff);
            *(uint4*)&K2[r][64 + s] = *(const uint4*)(ql_p + rowoff);
        }
        __syncthreads();
        if ((w >> 2) == half) {
            int rl = (w & 3) * 16 + (lane & 15);
#pragma unroll
            for (int ks = 0; ks < 4; ks++) {
                int kk = ks * 16 + (lane >> 4) * 8;
                ldsm4(qh[ks], smaddr(&K2[rl][kk]));
                ldsm4(ql[ks], smaddr(&K2[rl][64 + kk]));
            }
        }
        __syncthreads();
    }

    float Oacc[8][4] = {};
    float m0 = MASKVAL, m1 = MASKVAL;
    float l0 = 0.f, l1 = 0.f;

    const int irow0 = i0 + w * 16 + (lane >> 2);
    const int irow1 = irow0 + 8;
    const bool rf00 = irow0 >= off0, rf01 = irow0 >= off1;
    const bool rf10 = irow1 >= off0, rf11 = irow1 >= off1;

    const __nv_bfloat16* kh_p = qh_p + 1024;
    const __nv_bfloat16* kl_p = ql_p + 1024;
    const __nv_bfloat16* vh_p = qh_p + 2048;
    const __nv_bfloat16* vl_p = ql_p + 2048;

    for (int jt = 0; jt < 32; jt++) {
        int j0 = jt * 64;
        bool causal_p = (j0 <= i0 + 127);
        bool mod_p = ((i0 + 127 >= off0) && (j0 < end0)) ||
                     ((i0 + 127 >= off1) && (j0 < end1));
        if (!(causal_p || mod_p)) continue;

#pragma unroll
        for (int p = 0; p < 2; p++) {
            int f = p * 256 + tid;
            int r = f >> 3, s = (f & 7) * 8;
            long long rowoff = (long long)(j0 + r) * 3072 + s;
            CP_ASYNC16(smaddr(&K2[r][s]),      kh_p + rowoff, 16);
            CP_ASYNC16(smaddr(&K2[r][64 + s]), kl_p + rowoff, 16);
            CP_ASYNC16(smaddr(&V2[r][s]),      vh_p + rowoff, 16);
            CP_ASYNC16(smaddr(&V2[r][64 + s]), vl_p + rowoff, 16);
        }
        CP_COMMIT();
        CP_WAIT0();
        __syncthreads();

        float S[8][4] = {};
#pragma unroll
        for (int ks = 0; ks < 4; ks++) {
            unsigned kh_f[8][2], kl_f[8][2];
#pragma unroll
            for (int ntp = 0; ntp < 4; ntp++) {
                int row = ntp * 16 + (lane & 7) + ((lane >> 4) & 1) * 8;
                int col = ks * 16 + ((lane >> 3) & 1) * 8;
                unsigned r4[4];
                ldsm4(r4, smaddr(&K2[row][col]));
                kh_f[2*ntp][0] = r4[0]; kh_f[2*ntp][1] = r4[1];
                kh_f[2*ntp+1][0] = r4[2]; kh_f[2*ntp+1][1] = r4[3];
                ldsm4(r4, smaddr(&K2[row][64 + col]));
                kl_f[2*ntp][0] = r4[0]; kl_f[2*ntp][1] = r4[1];
                kl_f[2*ntp+1][0] = r4[2]; kl_f[2*ntp+1][1] = r4[3];
            }
#pragma unroll
            for (int nt = 0; nt < 8; nt++) {
                mma16(S[nt], qh[ks], kh_f[nt]);
                mma16(S[nt], qh[ks], kl_f[nt]);
                mma16(S[nt], ql[ks], kh_f[nt]);
            }
        }

        float mt0 = MASKVAL, mt1 = MASKVAL;
#pragma unroll
        for (int nt = 0; nt < 8; nt++) {
            int jc = j0 + nt * 8 + ((lane & 3) << 1);
#pragma unroll
            for (int e = 0; e < 4; e++) {
                int jj = jc + (e & 1);
                float s = softcap_tanh(S[nt][e]);
                bool keep;
                if (e < 2) keep = (irow0 >= jj) || (rf00 && jj < end0) || (rf01 && jj < end1);
                else       keep = (irow1 >= jj) || (rf10 && jj < end0) || (rf11 && jj < end1);
                s = keep ? s : MASKVAL;
                S[nt][e] = s;
                if (e < 2) mt0 = fmaxf(mt0, s); else mt1 = fmaxf(mt1, s);
            }
        }
        mt0 = fmaxf(mt0, __shfl_xor_sync(0xffffffffu, mt0, 1));
        mt0 = fmaxf(mt0, __shfl_xor_sync(0xffffffffu, mt0, 2));
        mt1 = fmaxf(mt1, __shfl_xor_sync(0xffffffffu, mt1, 1));
        mt1 = fmaxf(mt1, __shfl_xor_sync(0xffffffffu, mt1, 2));

        float mn0 = fmaxf(m0, mt0), mn1 = fmaxf(m1, mt1);
        float a0 = __expf(m0 - mn0), a1 = __expf(m1 - mn1);
        m0 = mn0; m1 = mn1;
        l0 *= a0; l1 *= a1;
#pragma unroll
        for (int nt = 0; nt < 8; nt++) {
            Oacc[nt][0] *= a0; Oacc[nt][1] *= a0;
            Oacc[nt][2] *= a1; Oacc[nt][3] *= a1;
        }

        unsigned ph_[4][4], pl_[4][4];
#pragma unroll
        for (int kt = 0; kt < 4; kt++) {
#pragma unroll
            for (int half = 0; half < 2; half++) {
                int nt = 2 * kt + half;
                float p0 = __expf(S[nt][0] - mn0);
                float p1 = __expf(S[nt][1] - mn0);
                float p2 = __expf(S[nt][2] - mn1);
                float p3 = __expf(S[nt][3] - mn1);
                l0 += p0 + p1; l1 += p2 + p3;
                __nv_bfloat16 h0,lo0,h1,lo1,h2,lo2,h3,lo3;
                split_bf16(p0, h0, lo0); split_bf16(p1, h1, lo1);
                split_bf16(p2, h2, lo2); split_bf16(p3, h3, lo3);
                ph_[kt][half*2+0] = pk2(h0, h1);
                ph_[kt][half*2+1] = pk2(h2, h3);
                pl_[kt][half*2+0] = pk2(lo0, lo1);
                pl_[kt][half*2+1] = pk2(lo2, lo3);
            }
        }

#pragma unroll
        for (int kt = 0; kt < 4; kt++) {
            unsigned vh_f[8][2], vl_f[8][2];
#pragma unroll
            for (int ntp = 0; ntp < 4; ntp++) {
                int row = kt * 16 + (lane & 15);
                int col = ntp * 16 + (lane >> 4) * 8;
                unsigned r4[4];
                ldsm4t(r4, smaddr(&V2[row][col]));
                vh_f[2*ntp][0] = r4[0]; vh_f[2*ntp][1] = r4[1];
                vh_f[2*ntp+1][0] = r4[2]; vh_f[2*ntp+1][1] = r4[3];
                ldsm4t(r4, smaddr(&V2[row][64 + col]));
                vl_f[2*ntp][0] = r4[0]; vl_f[2*ntp][1] = r4[1];
                vl_f[2*ntp+1][0] = r4[2]; vl_f[2*ntp+1][1] = r4[3];
            }
#pragma unroll
            for (int nt = 0; nt < 8; nt++) {
                mma16(Oacc[nt], ph_[kt], vh_f[nt]);
                mma16(Oacc[nt], ph_[kt], vl_f[nt]);
                mma16(Oacc[nt], pl_[kt], vh_f[nt]);
            }
        }
        __syncthreads();
    }

    float ls0 = l0 + __shfl_xor_sync(0xffffffffu, l0, 1);
    ls0 += __shfl_xor_sync(0xffffffffu, ls0, 2);
    float ls1 = l1 + __shfl_xor_sync(0xffffffffu, l1, 1);
    ls1 += __shfl_xor_sync(0xffffffffu, ls1, 2);
    float inv0 = 1.f / ls0, inv1 = 1.f / ls1;

    __nv_bfloat16* ohp = g_oh + (long long)b * SEQ * DIM + h * 64;
    __nv_bfloat16* olp = g_ol + (long long)b * SEQ * DIM + h * 64;
#pragma unroll
    for (int nt = 0; nt < 8; nt++) {
        int d = nt * 8 + ((lane & 3) << 1);
        float v00 = Oacc[nt][0] * inv0, v01 = Oacc[nt][1] * inv0;
        float v10 = Oacc[nt][2] * inv1, v11 = Oacc[nt][3] * inv1;
        __nv_bfloat16 hh, ll;
        split_bf16(v00, hh, ll);
        ohp[(long long)irow0 * DIM + d] = hh;     olp[(long long)irow0 * DIM + d] = ll;
        split_bf16(v01, hh, ll);
        ohp[(long long)irow0 * DIM + d + 1] = hh; olp[(long long)irow0 * DIM + d + 1] = ll;
        split_bf16(v10, hh, ll);
        ohp[(long long)irow1 * DIM + d] = hh;     olp[(long long)irow1 * DIM + d] = ll;
        split_bf16(v11, hh, ll);
        ohp[(long long)irow1 * DIM + d + 1] = hh; olp[(long long)irow1 * DIM + d + 1] = ll;
    }
}

// ---------------------------------------------------------------------------
// Fourier features -> split planes (zero pad cols >= 1025)
// ---------------------------------------------------------------------------
__global__ void fourier_kernel(const float* __restrict__ times,
                               const float* __restrict__ fw)
{
    long long idx = (long long)blockIdx.x * blockDim.x + threadIdx.x;
    if (idx >= (long long)TOK * FOURIER_LD) return;
    int t = (int)(idx / FOURIER_LD);
    int c = (int)(idx % FOURIER_LD);
    float out = 0.f;
    if (c == 0)         out = times[t];
    else if (c <= 512)  out = __sinf(times[t] * fw[c - 1] * TWO_PI);
    else if (c <= 1024) out = __cosf(times[t] * fw[c - 513] * TWO_PI);
    __nv_bfloat16 h, l;
    split_bf16(out, h, l);
    g_fh[idx] = h; g_fl[idx] = l;
}

// ---------------------------------------------------------------------------
// Fused LN -> adaptive modulation -> RMSnorm -> split h planes
// ---------------------------------------------------------------------------
__global__ void prenorm_kernel(const float* __restrict__ lng,
                               const float* __restrict__ rg,
                               const int* __restrict__ mp,
                               const float* __restrict__ gb)
{
    __shared__ float sm[8];
    int tok = blockIdx.x;
    int b = tok >> 11, n = tok & (SEQ - 1);
    bool mod = false;
#pragma unroll
    for (int m = 0; m < 2; m++) {
        int off = mp[b * 6 + m * 3 + 1];
        int len = mp[b * 6 + m * 3 + 2];
        if (n >= off && n < off + len) mod = true;
    }
    const float* xr = g_x + (long long)tok * DIM;
    int tid = threadIdx.x;

    float v[4];
    float s = 0.f, ss = 0.f;
#pragma unroll
    for (int i = 0; i < 4; i++) {
        float f = xr[tid + i * 256];
        v[i] = f; s += f; ss += f * f;
    }
    float mean = block_reduce_sum(s, sm) * (1.f / DIM);
    float ex2  = block_reduce_sum(ss, sm) * (1.f / DIM);
    float inv  = rsqrtf(ex2 - mean * mean + 1e-5f);

    const float* gbr = gb + (long long)tok * 2 * DIM;
    float hv[4];
    float ss2 = 0.f;
#pragma unroll
    for (int i = 0; i < 4; i++) {
        int c = tid + i * 256;
        float ln = (v[i] - mean) * inv;
        float hh;
        if (mod) hh = ln * (gbr[c] + 1.f) + gbr[DIM + c];
        else     hh = ln * (lng[c] + 1.f);
        hv[i] = hh; ss2 += hh * hh;
    }
    float nrm = sqrtf(block_reduce_sum(ss2, sm));
    float scale = 32.f / fmaxf(nrm, 1e-12f);
#pragma unroll
    for (int i = 0; i < 4; i++) {
        int c = tid + i * 256;
        float val = hv[i] * scale * (rg[c] + 1.f);
        __nv_bfloat16 hh, ll;
        split_bf16(val, hh, ll);
        g_hh[(long long)tok * DIM + c] = hh;
        g_hl[(long long)tok * DIM + c] = ll;
    }
}

// ---------------------------------------------------------------------------
// Final rmsnorm -> d_out
// ---------------------------------------------------------------------------
__global__ void final_rms_kernel(const float* __restrict__ fg,
                                 float* __restrict__ out)
{
    __shared__ float sm[8];
    int tok = blockIdx.x;
    const float* xr = g_x + (long long)tok * DIM;
    int tid = threadIdx.x;
    float v[4];
    float ss = 0.f;
#pragma unroll
    for (int i = 0; i < 4; i++) {
        v[i] = xr[tid + i * 256];
        ss += v[i] * v[i];
    }
    float nrm = sqrtf(block_reduce_sum(ss, sm));
    float scale = 32.f / fmaxf(nrm, 1e-12f);
    float* o = out + (long long)tok * DIM;
#pragma unroll
    for (int i = 0; i < 4; i++) {
        int c = tid + i * 256;
        o[c] = v[i] * scale * (fg[c] + 1.f);
    }
}

// ---------------------------------------------------------------------------
// Host side
// ---------------------------------------------------------------------------
#define TC5_DSMEM 197632u

static void launch_gemm_tc5(const __nv_bfloat16* Ah, const __nv_bfloat16* Al, int lda,
                            const __nv_bfloat16* Bh, const __nv_bfloat16* Bl, int ldb,
                            const float* bias, float* C, int ldc,
                            __nv_bfloat16* Csh, __nv_bfloat16* Csl,
                            int M, int N, int K, int act,
                            const int* skmp = nullptr,
                            const float* gate = nullptr, const float* ls = nullptr,
                            const int* mp = nullptr,
                            const MergedEp* mepp = nullptr)
{
    MergedEp mep = {};
    if (mepp) mep = *mepp;
    dim3 grid((N + 255) / 256, (M + 127) / 128, 1);
    gemm_tc5_kernel<<<grid, 256, TC5_DSMEM>>>(Ah, Al, lda, Bh, Bl, ldb, bias, C, ldc,
                                              Csh, Csl, M, N, K, act, skmp, gate, ls,
                                              mp, mep);
}

extern "C" void kernel_launch(void* const* d_in, const int* in_sizes, int n_in,
                              void* d_out, int out_size)
{
    const float* in_x        = (const float*)d_in[0];
    const float* in_times    = (const float*)d_in[1];
    const float* in_rot      = (const float*)d_in[2];
    const float* in_fw       = (const float*)d_in[3];
    const float* in_time_w   = (const float*)d_in[4];
    const float* in_time_b   = (const float*)d_in[5];
    const float* a_film_w    = (const float*)d_in[6];
    const float* a_film_b    = (const float*)d_in[7];
    const float* a_az_w      = (const float*)d_in[8];
    const float* a_az_b      = (const float*)d_in[9];
    const float* a_ln_g      = (const float*)d_in[10];
    const float* a_ls        = (const float*)d_in[11];
    const float* a_rms_g     = (const float*)d_in[12];
    const float* w_qkv       = (const float*)d_in[13];
    const float* w_out       = (const float*)d_in[14];
    const float* f_film_w    = (const float*)d_in[15];
    const float* f_film_b    = (const float*)d_in[16];
    const float* f_az_w      = (const float*)d_in[17];
    const float* f_az_b      = (const float*)d_in[18];
    const float* f_ln_g      = (const float*)d_in[19];
    const float* f_ls        = (const float*)d_in[20];
    const float* f_rms_g     = (const float*)d_in[21];
    const float* ff_w1       = (const float*)d_in[22];
    const float* ff_b1       = (const float*)d_in[23];
    const float* ff_w2       = (const float*)d_in[24];
    const float* ff_b2       = (const float*)d_in[25];
    const float* final_g     = (const float*)d_in[26];
    const int*   mod_pos     = (const int*)d_in[27];

    cudaFuncSetAttribute(gemm_tc5_kernel,
                         cudaFuncAttributeMaxDynamicSharedMemorySize, TC5_DSMEM);

    float *p_gba, *p_gbf, *p_gatea, *p_gatef, *p_x;
    __nv_bfloat16 *p_fh, *p_fl, *p_condh, *p_condl, *p_hh, *p_hl,
                  *p_qkvh, *p_qkvl, *p_oh, *p_ol, *p_acth, *p_actl,
                  *p_wh, *p_wl;
    cudaGetSymbolAddress((void**)&p_gba,   g_gba);
    cudaGetSymbolAddress((void**)&p_gbf,   g_gbf);
    cudaGetSymbolAddress((void**)&p_gatea, g_gatea);
    cudaGetSymbolAddress((void**)&p_gatef, g_gatef);
    cudaGetSymbolAddress((void**)&p_x,     g_x);
    cudaGetSymbolAddress((void**)&p_fh,    g_fh);
    cudaGetSymbolAddress((void**)&p_fl,    g_fl);
    cudaGetSymbolAddress((void**)&p_condh, g_condh);
    cudaGetSymbolAddress((void**)&p_condl, g_condl);
    cudaGetSymbolAddress((void**)&p_hh,    g_hh);
    cudaGetSymbolAddress((void**)&p_hl,    g_hl);
    cudaGetSymbolAddress((void**)&p_qkvh,  g_qkvh);
    cudaGetSymbolAddress((void**)&p_qkvl,  g_qkvl);
    cudaGetSymbolAddress((void**)&p_oh,    g_oh);
    cudaGetSymbolAddress((void**)&p_ol,    g_ol);
    cudaGetSymbolAddress((void**)&p_acth,  g_acth);
    cudaGetSymbolAddress((void**)&p_actl,  g_actl);
    cudaGetSymbolAddress((void**)&p_wh,    g_wh);
    cudaGetSymbolAddress((void**)&p_wl,    g_wl);

    cudaMemcpyAsync(p_x, in_x, (size_t)TOK * DIM * sizeof(float),
                    cudaMemcpyDeviceToDevice, 0);

    // ------------- weight split + transpose -------------
    long long wo = 0;
    auto wregT = [&](const float* src, int R, int C, int Rpad, int pmode) -> long long {
        long long o = wo;
        dim3 grid((C + 63) / 64, (Rpad + 63) / 64);
        wsplitT_kernel<<<grid, 256>>>(src, p_wh + o, p_wl + o, R, C, Rpad, pmode, DFF);
        wo += (long long)C * Rpad;
        return o;
    };
    long long o_timew = wregT(in_time_w, 1025, DCOND, FOURIER_LD, 0);
    long long o_condw[2], o_qkvw[2], o_woutw[2], o_ff1w[2], o_ff2w[2];
    for (int l = 0; l < DEPTH; l++) {
        // merged cond weights: [film_a(2048) | az_a(1024) | film_f(2048) | az_f(1024)]
        o_condw[l] = wregT(a_film_w + (long long)l * DCOND * 2 * DIM, DCOND, 2 * DIM, DCOND, 0);
        wregT(a_az_w   + (long long)l * DCOND * DIM,     DCOND, DIM, DCOND, 0);
        wregT(f_film_w + (long long)l * DCOND * 2 * DIM, DCOND, 2 * DIM, DCOND, 0);
        wregT(f_az_w   + (long long)l * DCOND * DIM,     DCOND, DIM, DCOND, 0);
        o_qkvw[l]  = wregT(w_qkv  + (long long)l * DIM * 3 * DIM, DIM, 3 * DIM, DIM, 0);
        o_woutw[l] = wregT(w_out  + (long long)l * DIM * DIM,     DIM, DIM, DIM, 0);
        o_ff1w[l]  = wregT(ff_w1  + (long long)l * DIM * 2 * DFF, DIM, 2 * DFF, DIM,
                           /*GEGLU interleave*/1);
        o_ff2w[l]  = wregT(ff_w2  + (long long)l * DFF * DIM,     DFF, DIM, ACT_LD, 0);
    }

    // ------------- time conditioning -------------
    {
        long long tot = (long long)TOK * FOURIER_LD;
        fourier_kernel<<<(unsigned)((tot + 255) / 256), 256>>>(in_times, in_fw);
        launch_gemm_tc5(p_fh, p_fl, FOURIER_LD,
                        p_wh + o_timew, p_wl + o_timew, FOURIER_LD,
                        in_time_b, nullptr, DCOND,
                        p_condh, p_condl,
                        TOK, DCOND, 1025, /*silu->split*/5);
    }

    for (int l = 0; l < DEPTH; l++) {
        const float* lnG[2]   = { a_ln_g + (long long)l * DIM,
                                  f_ln_g + (long long)l * DIM };
        const float* lsP[2]   = { a_ls + (long long)l * DIM,
                                  f_ls + (long long)l * DIM };
        const float* rmsG[2]  = { a_rms_g + (long long)l * DIM,
                                  f_rms_g + (long long)l * DIM };

        // ======== merged cond GEMM: film_a | az_a | film_f | az_f ========
        MergedEp mep;
        mep.bf0 = a_film_b + (long long)l * 2 * DIM;
        mep.ba0 = a_az_b   + (long long)l * DIM;
        mep.bf1 = f_film_b + (long long)l * 2 * DIM;
        mep.ba1 = f_az_b   + (long long)l * DIM;
        mep.gb0 = p_gba;  mep.gt0 = p_gatea;
        mep.gb1 = p_gbf;  mep.gt1 = p_gatef;
        launch_gemm_tc5(p_condh, p_condl, DCOND,
                        p_wh + o_condw[l], p_wl + o_condw[l], DCOND,
                        nullptr, nullptr, 0, nullptr, nullptr,
                        TOK, 6 * DIM, DCOND, /*merged*/7, mod_pos,
                        nullptr, nullptr, nullptr, &mep);

        // ================= attention block =================
        prenorm_kernel<<<TOK, 256>>>(lnG[0], rmsG[0], mod_pos, p_gba);

        // qkv GEMM with fused rotary + split epilogue
        launch_gemm_tc5(p_hh, p_hl, DIM,
                        p_wh + o_qkvw[l], p_wl + o_qkvw[l], DIM,
                        in_rot, nullptr, 0, p_qkvh, p_qkvl,
                        TOK, 3 * DIM, DIM, /*qkv-rotary*/8);

        {
            dim3 fg(SEQ / 128, BATCH * HEADS);
            flash_kernel<<<fg, 256>>>(mod_pos);
        }

        // wout with fused gated residual into g_x
        launch_gemm_tc5(p_oh, p_ol, DIM,
                        p_wh + o_woutw[l], p_wl + o_woutw[l], DIM,
                        nullptr, p_x, DIM, nullptr, nullptr,
                        TOK, DIM, DIM, 4, nullptr, p_gatea, lsP[0], mod_pos);

        // ================= feed-forward block =================
        prenorm_kernel<<<TOK, 256>>>(lnG[1], rmsG[1], mod_pos, p_gbf);

        // ff1 GEMM (interleaved weights) with fused bias+GEGLU+split epilogue
        launch_gemm_tc5(p_hh, p_hl, DIM,
                        p_wh + o_ff1w[l], p_wl + o_ff1w[l], DIM,
                        ff_b1 + (long long)l * 2 * DFF, nullptr, 0,
                        p_acth, p_actl,
                        TOK, 2 * DFF, DIM, /*geglu*/9);

        // ff2 with bias + fused gated residual into g_x
        launch_gemm_tc5(p_acth, p_actl, ACT_LD,
                        p_wh + o_ff2w[l], p_wl + o_ff2w[l], ACT_LD,
                        ff_b2 + (long long)l * DIM, p_x, DIM, nullptr, nullptr,
                        TOK, DIM, DFF, 6, nullptr, p_gatef, lsP[1], mod_pos);
    }

    final_rms_kernel<<<TOK, 256>>>(final_g, (float*)d_out);

    (void)in_sizes; (void)n_in; (void)out_size;
}

// round 17
// speedup vs baseline: 1.4907x; 1.4907x over previous
#include <cuda_runtime.h>
#include <cuda_bf16.h>
#include <math.h>

// ---------------------------------------------------------------------------
// Problem constants
// ---------------------------------------------------------------------------
#define BATCH   2
#define SEQ     2048
#define DIM     1024
#define HEADS   16
#define DHEAD   64
#define DEPTH   2
#define DCOND   4096
#define DFF     2730
#define TOK     (BATCH*SEQ)
#define SOFTCAP 50.0f
#define QK_SCALE 0.125f
#define TWO_PI  6.2831853071795864769f
#define MASKVAL (-1.0e4f)

#define FOURIER_LD 1032       // 1025 padded to multiple of 8
#define ACT_LD     2736       // 2730 padded to multiple of 8

// tcgen05 only exists in arch-specific (sm_103a) device passes.
#if defined(__CUDA_ARCH_FEAT_SM103_ALL) || \
    (defined(__CUDA_ARCH_SPECIFIC__) && (__CUDA_ARCH_SPECIFIC__ == 1030))
#define HAS_TC5 1
#else
#define HAS_TC5 0
#endif

// Merged cond-GEMM epilogue pointers (act == 7)
struct MergedEp {
    const float* bf0; const float* ba0; const float* bf1; const float* ba1;
    float* gb0; float* gt0; float* gb1; float* gt1;
};

// ---------------------------------------------------------------------------
// Scratch (static device globals; no allocation allowed)
// ---------------------------------------------------------------------------
__device__ float g_qkv   [(size_t)TOK * 3 * DIM];
__device__ float g_gba   [(size_t)TOK * 2 * DIM];
__device__ float g_gbf   [(size_t)TOK * 2 * DIM];
__device__ float g_gatea [(size_t)TOK * DIM];
__device__ float g_gatef [(size_t)TOK * DIM];
__device__ float g_ff1   [(size_t)TOK * 2 * DFF];
__device__ float g_x     [(size_t)TOK * DIM];

__device__ __nv_bfloat16 g_fh   [(size_t)TOK * FOURIER_LD];
__device__ __nv_bfloat16 g_fl   [(size_t)TOK * FOURIER_LD];
__device__ __nv_bfloat16 g_condh[(size_t)TOK * DCOND];
__device__ __nv_bfloat16 g_condl[(size_t)TOK * DCOND];
__device__ __nv_bfloat16 g_hh   [(size_t)TOK * DIM];
__device__ __nv_bfloat16 g_hl   [(size_t)TOK * DIM];
__device__ __nv_bfloat16 g_qkvh [(size_t)TOK * 3 * DIM];
__device__ __nv_bfloat16 g_qkvl [(size_t)TOK * 3 * DIM];
__device__ __nv_bfloat16 g_oh   [(size_t)TOK * DIM];
__device__ __nv_bfloat16 g_ol   [(size_t)TOK * DIM];
__device__ __nv_bfloat16 g_acth [(size_t)TOK * ACT_LD];
__device__ __nv_bfloat16 g_actl [(size_t)TOK * ACT_LD];

// all weights, split TRANSPOSED ([N,Kpad], K-major) once per launch
__device__ __nv_bfloat16 g_wh[80000000];
__device__ __nv_bfloat16 g_wl[80000000];

// ---------------------------------------------------------------------------
// Primitives
// ---------------------------------------------------------------------------
__device__ __forceinline__ void split_bf16(float x, __nv_bfloat16& h, __nv_bfloat16& l) {
    h = __float2bfloat16(x);
    l = __float2bfloat16(x - __bfloat162float(h));
}
__device__ __forceinline__ unsigned pk2(__nv_bfloat16 a, __nv_bfloat16 b) {
    unsigned short ua = __bfloat16_as_ushort(a), ub = __bfloat16_as_ushort(b);
    return ((unsigned)ub << 16) | (unsigned)ua;
}
__device__ __forceinline__ unsigned smaddr(const void* p) {
    return (unsigned)__cvta_generic_to_shared(p);
}
__device__ __forceinline__ void ldsm4(unsigned r[4], unsigned addr) {
    asm volatile("ldmatrix.sync.aligned.m8n8.x4.shared.b16 {%0,%1,%2,%3}, [%4];"
                 : "=r"(r[0]), "=r"(r[1]), "=r"(r[2]), "=r"(r[3]) : "r"(addr));
}
__device__ __forceinline__ void ldsm4t(unsigned r[4], unsigned addr) {
    asm volatile("ldmatrix.sync.aligned.m8n8.x4.trans.shared.b16 {%0,%1,%2,%3}, [%4];"
                 : "=r"(r[0]), "=r"(r[1]), "=r"(r[2]), "=r"(r[3]) : "r"(addr));
}
__device__ __forceinline__ void mma16(float acc[4], const unsigned a[4], const unsigned b[2]) {
    asm volatile(
        "mma.sync.aligned.m16n8k16.row.col.f32.bf16.bf16.f32 "
        "{%0,%1,%2,%3},{%4,%5,%6,%7},{%8,%9},{%0,%1,%2,%3};"
        : "+f"(acc[0]), "+f"(acc[1]), "+f"(acc[2]), "+f"(acc[3])
        : "r"(a[0]), "r"(a[1]), "r"(a[2]), "r"(a[3]), "r"(b[0]), "r"(b[1]));
}
#define CP_ASYNC16(dst, src, bytes) \
    asm volatile("cp.async.cg.shared.global [%0], [%1], 16, %2;" :: \
                 "r"(dst), "l"(src), "r"(bytes))
#define CP_COMMIT()  asm volatile("cp.async.commit_group;")
#define CP_WAIT0()   asm volatile("cp.async.wait_group 0;")
#define CP_WAIT1()   asm volatile("cp.async.wait_group 1;")

__device__ __forceinline__ void mbar_init(unsigned addr, unsigned cnt) {
    asm volatile("mbarrier.init.shared.b64 [%0], %1;" :: "r"(addr), "r"(cnt) : "memory");
}
__device__ __forceinline__ void mbar_wait(unsigned addr, unsigned parity) {
    asm volatile(
        "{\n\t.reg .pred P;\n\t"
        "W_%=:\n\t"
        "mbarrier.try_wait.parity.acquire.cta.shared::cta.b64 P, [%0], %1, 0x989680;\n\t"
        "@P bra D_%=;\n\t"
        "bra W_%=;\n\t"
        "D_%=:\n\t}"
        :: "r"(addr), "r"(parity) : "memory");
}
#define FENCE_PROXY() asm volatile("fence.proxy.async.shared::cta;" ::: "memory")

#if HAS_TC5
// ---- tcgen05 primitives (cg1), only compiled in arch-specific pass ----
__device__ __forceinline__ unsigned long long mkdesc(unsigned a) {
    // SW128, version=1 (Blackwell), SBO=64, LBO=1, K-major
    const unsigned long long B =
        (2ULL << 61) | (1ULL << 46) | (64ULL << 32) | (1ULL << 16);
    return B | (unsigned long long)((a >> 4) & 0x3FFF);
}
// idesc kind::f16: f32 accum, bf16 a/b, M=128, N=128
#define TC5_IDESC 0x8200490u

__device__ __forceinline__ void tc5_mma(unsigned d, unsigned long long ad,
                                        unsigned long long bd, unsigned en) {
    asm volatile(
        "{\n\t.reg .pred p;\n\t"
        "setp.ne.u32 p, %4, 0;\n\t"
        "tcgen05.mma.cta_group::1.kind::f16 [%0], %1, %2, %3, {%5,%5,%5,%5}, p;\n\t"
        "}"
        :: "r"(d), "l"(ad), "l"(bd), "r"(TC5_IDESC), "r"(en), "r"(0u)
        : "memory");
}
__device__ __forceinline__ void tc5_commit(unsigned mbar) {
    asm volatile(
        "tcgen05.commit.cta_group::1.mbarrier::arrive::one.shared::cluster.b64 [%0];"
        :: "r"(mbar) : "memory");
}
#define TC5_FENCE_AFTER() asm volatile("tcgen05.fence::after_thread_sync;" ::: "memory")
#define TC5_WAIT_LD() asm volatile("tcgen05.wait::ld.sync.aligned;" ::: "memory")

__device__ __forceinline__ void ldtm_x32(unsigned* r, unsigned addr) {
    asm volatile(
        "tcgen05.ld.sync.aligned.32x32b.x32.b32 "
        "{%0,%1,%2,%3,%4,%5,%6,%7,"
        "%8,%9,%10,%11,%12,%13,%14,%15,"
        "%16,%17,%18,%19,%20,%21,%22,%23,"
        "%24,%25,%26,%27,%28,%29,%30,%31}, [%32];"
        : "=r"(r[0]),  "=r"(r[1]),  "=r"(r[2]),  "=r"(r[3]),
          "=r"(r[4]),  "=r"(r[5]),  "=r"(r[6]),  "=r"(r[7]),
          "=r"(r[8]),  "=r"(r[9]),  "=r"(r[10]), "=r"(r[11]),
          "=r"(r[12]), "=r"(r[13]), "=r"(r[14]), "=r"(r[15]),
          "=r"(r[16]), "=r"(r[17]), "=r"(r[18]), "=r"(r[19]),
          "=r"(r[20]), "=r"(r[21]), "=r"(r[22]), "=r"(r[23]),
          "=r"(r[24]), "=r"(r[25]), "=r"(r[26]), "=r"(r[27]),
          "=r"(r[28]), "=r"(r[29]), "=r"(r[30]), "=r"(r[31])
        : "r"(addr));
}
#endif // HAS_TC5

#define SWZ(o) ((o) ^ (((o) >> 3) & 0x70))

__device__ __forceinline__ float softcap_tanh(float S) {
    float x = S * (1.0f / SOFTCAP);
    float u = x * x;
    if (u <= 0.25f) {
        float p = -0.33333333f + u * (0.13333333f + u * (-0.05396825f +
                  u * (0.02186949f - u * 0.00886322f)));
        return S * (1.0f + u * p);
    } else {
        float ax = fminf(fabsf(x), 20.f);
        float t = __expf(-2.f * ax);
        float r = __fdividef(1.f - t, 1.f + t);
        return copysignf(r, x) * SOFTCAP;
    }
}

__device__ __forceinline__ float block_reduce_sum(float v, float* sm) {
    int lane = threadIdx.x & 31, warp = threadIdx.x >> 5;
#pragma unroll
    for (int o = 16; o; o >>= 1) v += __shfl_xor_sync(0xffffffffu, v, o);
    if (lane == 0) sm[warp] = v;
    __syncthreads();
    if (warp == 0) {
        v = (lane < 8) ? sm[lane] : 0.f;
#pragma unroll
        for (int o = 4; o; o >>= 1) v += __shfl_xor_sync(0xffffffffu, v, o);
        if (lane == 0) sm[0] = v;
    }
    __syncthreads();
    float r = sm[0];
    __syncthreads();
    return r;
}

// ---------------------------------------------------------------------------
// Weight split + transpose: src f32 [R,C] -> dh/dl bf16 [C, Rpad]
// 64x64 tiles, float4 loads, packed uint2 stores.
// ---------------------------------------------------------------------------
__global__ void wsplitT_kernel(const float* __restrict__ src,
                               __nv_bfloat16* __restrict__ dh,
                               __nv_bfloat16* __restrict__ dl,
                               int R, int C, int Rpad)
{
    __shared__ float ts[64][65];
    int t = threadIdx.x;
    int c0 = blockIdx.x * 64, r0 = blockIdx.y * 64;
#pragma unroll
    for (int i = 0; i < 4; i++) {
        int q = i * 256 + t;
        int r = q >> 4, c4 = (q & 15) * 4;
        int sr = r0 + r, sc = c0 + c4;
        float4 v = make_float4(0.f, 0.f, 0.f, 0.f);
        if (sr < R && sc < C)
            v = *(const float4*)(src + (size_t)sr * C + sc);
        ts[r][c4 + 0] = v.x; ts[r][c4 + 1] = v.y;
        ts[r][c4 + 2] = v.z; ts[r][c4 + 3] = v.w;
    }
    __syncthreads();
#pragma unroll
    for (int i = 0; i < 4; i++) {
        int q = i * 256 + t;
        int c = q >> 4, rq = (q & 15) * 4;
        int dc = c0 + c, dr = r0 + rq;
        if (dc < C && dr < Rpad) {
            __nv_bfloat16 h[4], l[4];
#pragma unroll
            for (int e = 0; e < 4; e++) split_bf16(ts[rq + e][c], h[e], l[e]);
            *(uint2*)&dh[(size_t)dc * Rpad + dr] =
                make_uint2(pk2(h[0], h[1]), pk2(h[2], h[3]));
            *(uint2*)&dl[(size_t)dc * Rpad + dr] =
                make_uint2(pk2(l[0], l[1]), pk2(l[2], l[3]));
        }
    }
}

// ---------------------------------------------------------------------------
// GEMM: C[M,N] = epilogue(A[M,K] @ WT[N,K]^T [+bias])
// Arch-specific pass: tcgen05 SS, CTA tile 128x256, BK=64, 3-term bf16 split.
// act: 0 plain f32, 1 +bias f32, 4 gated residual (C=g_x+=),
//      5 +bias silu -> split bf16 out, 6 +bias gated residual,
//      7 merged cond epilogue (MergedEp)
// Epilogues vectorized (float4/uint2) on full 64-col groups.
// ---------------------------------------------------------------------------
__global__ __launch_bounds__(256, 1)
void gemm_tc5_kernel(
    const __nv_bfloat16* __restrict__ Ah, const __nv_bfloat16* __restrict__ Al, int lda,
    const __nv_bfloat16* __restrict__ Bh, const __nv_bfloat16* __restrict__ Bl, int ldb,
    const float* __restrict__ bias,
    float* __restrict__ C, int ldc,
    __nv_bfloat16* __restrict__ Csh, __nv_bfloat16* __restrict__ Csl,
    int M, int N, int K, int act,
    const int* __restrict__ skmp,
    const float* __restrict__ gate, const float* __restrict__ ls,
    const int* __restrict__ mp, MergedEp mep)
{
    const int row0 = blockIdx.y * 128, col0 = blockIdx.x * 256;
    if (skmp) {
        int bb = row0 >> 11;
        int n0 = row0 & (SEQ - 1);
        int o0 = skmp[bb*6+1], L0 = skmp[bb*6+2];
        int o1 = skmp[bb*6+4], L1 = skmp[bb*6+5];
        bool hit = (n0 + 127 >= o0 && n0 < o0 + L0) ||
                   (n0 + 127 >= o1 && n0 < o1 + L1);
        if (!hit) return;
    }

    const int tid = threadIdx.x;
    const int wid = tid >> 5, lane = tid & 31;

#if HAS_TC5
    // ===================== tcgen05 path (128x256) =====================
    extern __shared__ __align__(16) char dsm_raw[];
    char* dsm = (char*)(((unsigned long long)dsm_raw + 1023) & ~1023ULL);
    auto planeA = [&](int s, int p) -> char* { return dsm + s * 98304 + p * 16384; };
    auto planeB = [&](int s, int p) -> char* { return dsm + s * 98304 + 32768 + p * 32768; };

    __shared__ unsigned sh_tmem[1];
    __shared__ __align__(8) unsigned long long sh_mbar[2];

    if (wid == 0)
        asm volatile("tcgen05.alloc.cta_group::1.sync.aligned.shared::cta.b32 [%0], %1;"
                     :: "r"(smaddr(sh_tmem)), "r"(512u) : "memory");
    if (tid == 0) { mbar_init(smaddr(&sh_mbar[0]), 1); mbar_init(smaddr(&sh_mbar[1]), 1); }
    __syncthreads();
    unsigned tmem_base;
    asm volatile("ld.shared.b32 %0, [%1];" : "=r"(tmem_base) : "r"(smaddr(sh_tmem)));

    const int nk = (K + 63) >> 6;

    auto load_stage = [&](int k0, int s) {
        unsigned baseA_h = smaddr(planeA(s, 0));
        unsigned baseA_l = smaddr(planeA(s, 1));
        unsigned baseB_h = smaddr(planeB(s, 0));
        unsigned baseB_l = smaddr(planeB(s, 1));
#pragma unroll
        for (int i = 0; i < 4; i++) {
            int q = tid + i * 256;
            int r = q >> 3;
            int cb = (q & 7) * 16;
            unsigned sw = SWZ(r * 128 + cb);
            int kg = k0 + (cb >> 1);
            int abytes = (kg < lda) ? 16 : 0;
            const __nv_bfloat16* pah = abytes ? Ah + (size_t)(row0 + r) * lda + kg : Ah;
            const __nv_bfloat16* pal = abytes ? Al + (size_t)(row0 + r) * lda + kg : Al;
            CP_ASYNC16(baseA_h + sw, pah, abytes);
            CP_ASYNC16(baseA_l + sw, pal, abytes);
        }
#pragma unroll
        for (int i = 0; i < 8; i++) {
            int q = tid + i * 256;
            int r = q >> 3;
            int cb = (q & 7) * 16;
            unsigned sw = SWZ(r * 128 + cb);
            int kg = k0 + (cb >> 1);
            int bbytes = ((col0 + r) < N && kg < ldb) ? 16 : 0;
            const __nv_bfloat16* pbh = bbytes ? Bh + (size_t)(col0 + r) * ldb + kg : Bh;
            const __nv_bfloat16* pbl = bbytes ? Bl + (size_t)(col0 + r) * ldb + kg : Bl;
            CP_ASYNC16(baseB_h + sw, pbh, bbytes);
            CP_ASYNC16(baseB_l + sw, pbl, bbytes);
        }
        CP_COMMIT();
    };

    int phs[2] = {0, 0};
    load_stage(0, 0);

    for (int t = 0; t < nk; t++) {
        int b = t & 1;
        if (t + 1 < nk) {
            int nb = b ^ 1;
            if (t >= 1) { mbar_wait(smaddr(&sh_mbar[nb]), phs[nb]); phs[nb] ^= 1; }
            load_stage((t + 1) * 64, nb);
            CP_WAIT1();
        } else {
            CP_WAIT0();
        }
        FENCE_PROXY();
        __syncthreads();

        if (tid == 0) {
            unsigned long long dAh = mkdesc(smaddr(planeA(b, 0)));
            unsigned long long dAl = mkdesc(smaddr(planeA(b, 1)));
            unsigned long long dBh = mkdesc(smaddr(planeB(b, 0)));
            unsigned long long dBl = mkdesc(smaddr(planeB(b, 1)));
#pragma unroll
            for (int nh = 0; nh < 2; nh++) {
                unsigned d = tmem_base + nh * 128;
                unsigned long long bh = dBh + nh * 1024;
                unsigned long long bl = dBl + nh * 1024;
#pragma unroll
                for (int ks = 0; ks < 4; ks++) {
                    unsigned long long oa = ks * 2;
                    unsigned en0 = (t == 0 && ks == 0) ? 0u : 1u;
                    tc5_mma(d, dAh + oa, bh + oa, en0);
                    tc5_mma(d, dAh + oa, bl + oa, 1u);
                    tc5_mma(d, dAl + oa, bh + oa, 1u);
                }
            }
            tc5_commit(smaddr(&sh_mbar[b]));
        }
        // no trailing __syncthreads: cross-buffer hazards covered by mbar parity
    }

    {
        int lb = (nk - 1) & 1;
        mbar_wait(smaddr(&sh_mbar[lb]), phs[lb]);
    }
    TC5_FENCE_AFTER();

    // epilogue: warp w -> subpartition rows (w&3)*32+lane, col group (w>>2)*64
    {
        int cb0 = (wid >> 2) * 64;
        int rr = row0 + (wid & 3) * 32 + lane;
        bool mod = false;
        if (act == 4 || act == 6) {
            int bb = rr >> 11, nn = rr & (SEQ - 1);
            int o0 = mp[bb*6+1], e0 = o0 + mp[bb*6+2];
            int o1 = mp[bb*6+4], e1 = o1 + mp[bb*6+5];
            mod = (nn >= o0 && nn < e0) || (nn >= o1 && nn < e1);
        }
#pragma unroll
        for (int nh = 0; nh < 2; nh++) {
            unsigned dreg[64];
            ldtm_x32(dreg,      tmem_base + nh * 128 + cb0);
            ldtm_x32(dreg + 32, tmem_base + nh * 128 + cb0 + 32);
            TC5_WAIT_LD();

            const int bc = col0 + nh * 128 + cb0;
            const bool full = (bc + 64 <= N);

            if (act == 0 && full) {
                float* dst = C + (long long)rr * ldc + bc;
#pragma unroll
                for (int j = 0; j < 64; j += 4) {
                    float4 v4;
                    v4.x = __uint_as_float(dreg[j]);
                    v4.y = __uint_as_float(dreg[j+1]);
                    v4.z = __uint_as_float(dreg[j+2]);
                    v4.w = __uint_as_float(dreg[j+3]);
                    *(float4*)(dst + j) = v4;
                }
            } else if (act == 1 && full) {
                float* dst = C + (long long)rr * ldc + bc;
#pragma unroll
                for (int j = 0; j < 64; j += 4) {
                    float4 b4 = *(const float4*)(bias + bc + j);
                    float4 v4;
                    v4.x = __uint_as_float(dreg[j])   + b4.x;
                    v4.y = __uint_as_float(dreg[j+1]) + b4.y;
                    v4.z = __uint_as_float(dreg[j+2]) + b4.z;
                    v4.w = __uint_as_float(dreg[j+3]) + b4.w;
                    *(float4*)(dst + j) = v4;
                }
            } else if (act == 5 && full) {
                long long base = (long long)rr * ldc + bc;
#pragma unroll
                for (int j = 0; j < 64; j += 4) {
                    __nv_bfloat16 h[4], l[4];
#pragma unroll
                    for (int e = 0; e < 4; e++) {
                        float s = __uint_as_float(dreg[j+e]) + bias[bc + j + e];
                        s = s / (1.f + __expf(-s));
                        split_bf16(s, h[e], l[e]);
                    }
                    *(uint2*)&Csh[base + j] = make_uint2(pk2(h[0],h[1]), pk2(h[2],h[3]));
                    *(uint2*)&Csl[base + j] = make_uint2(pk2(l[0],l[1]), pk2(l[2],l[3]));
                }
            } else if (act == 7) {
                // region uniform per 64-col group (boundaries multiples of 64)
                if (bc < 2048) {
                    float* dst = mep.gb0 + (long long)rr * 2048 + bc;
#pragma unroll
                    for (int j = 0; j < 64; j += 4) {
                        float4 b4 = *(const float4*)(mep.bf0 + bc + j);
                        float4 v4;
                        v4.x = __uint_as_float(dreg[j])   + b4.x;
                        v4.y = __uint_as_float(dreg[j+1]) + b4.y;
                        v4.z = __uint_as_float(dreg[j+2]) + b4.z;
                        v4.w = __uint_as_float(dreg[j+3]) + b4.w;
                        *(float4*)(dst + j) = v4;
                    }
                } else if (bc < 3072) {
                    int c0b = bc - 2048;
                    float* dst = mep.gt0 + (long long)rr * 1024 + c0b;
#pragma unroll
                    for (int j = 0; j < 64; j += 4) {
                        float4 b4 = *(const float4*)(mep.ba0 + c0b + j);
                        float4 v4;
                        v4.x = 1.f / (1.f + __expf(-(__uint_as_float(dreg[j])   + b4.x)));
                        v4.y = 1.f / (1.f + __expf(-(__uint_as_float(dreg[j+1]) + b4.y)));
                        v4.z = 1.f / (1.f + __expf(-(__uint_as_float(dreg[j+2]) + b4.z)));
                        v4.w = 1.f / (1.f + __expf(-(__uint_as_float(dreg[j+3]) + b4.w)));
                        *(float4*)(dst + j) = v4;
                    }
                } else if (bc < 5120) {
                    int c0b = bc - 3072;
                    float* dst = mep.gb1 + (long long)rr * 2048 + c0b;
#pragma unroll
                    for (int j = 0; j < 64; j += 4) {
                        float4 b4 = *(const float4*)(mep.bf1 + c0b + j);
                        float4 v4;
                        v4.x = __uint_as_float(dreg[j])   + b4.x;
                        v4.y = __uint_as_float(dreg[j+1]) + b4.y;
                        v4.z = __uint_as_float(dreg[j+2]) + b4.z;
                        v4.w = __uint_as_float(dreg[j+3]) + b4.w;
                        *(float4*)(dst + j) = v4;
                    }
                } else {
                    int c0b = bc - 5120;
                    float* dst = mep.gt1 + (long long)rr * 1024 + c0b;
#pragma unroll
                    for (int j = 0; j < 64; j += 4) {
                        float4 b4 = *(const float4*)(mep.ba1 + c0b + j);
                        float4 v4;
                        v4.x = 1.f / (1.f + __expf(-(__uint_as_float(dreg[j])   + b4.x)));
                        v4.y = 1.f / (1.f + __expf(-(__uint_as_float(dreg[j+1]) + b4.y)));
                        v4.z = 1.f / (1.f + __expf(-(__uint_as_float(dreg[j+2]) + b4.z)));
                        v4.w = 1.f / (1.f + __expf(-(__uint_as_float(dreg[j+3]) + b4.w)));
                        *(float4*)(dst + j) = v4;
                    }
                }
            } else if ((act == 4 || act == 6) && full) {
                float* dst = C + (long long)rr * ldc + bc;
#pragma unroll
                for (int j = 0; j < 64; j += 4) {
                    float4 v4;
                    v4.x = __uint_as_float(dreg[j]);
                    v4.y = __uint_as_float(dreg[j+1]);
                    v4.z = __uint_as_float(dreg[j+2]);
                    v4.w = __uint_as_float(dreg[j+3]);
                    if (act == 6) {
                        float4 b4 = *(const float4*)(bias + bc + j);
                        v4.x += b4.x; v4.y += b4.y; v4.z += b4.z; v4.w += b4.w;
                    }
                    float4 s4;
                    if (mod) {
                        s4 = *(const float4*)(gate + (long long)rr * N + bc + j);
                    } else {
                        float4 t4 = *(const float4*)(ls + bc + j);
                        s4.x = t4.x + 1.f; s4.y = t4.y + 1.f;
                        s4.z = t4.z + 1.f; s4.w = t4.w + 1.f;
                    }
                    float4 c4 = *(float4*)(dst + j);
                    c4.x += v4.x * s4.x; c4.y += v4.y * s4.y;
                    c4.z += v4.z * s4.z; c4.w += v4.w * s4.w;
                    *(float4*)(dst + j) = c4;
                }
            } else {
                // scalar fallback (partial tiles)
#pragma unroll 4
                for (int j = 0; j < 64; j++) {
                    int cc = bc + j;
                    if (cc >= N) break;
                    float v = __uint_as_float(dreg[j]);
                    long long idx = (long long)rr * ldc + cc;
                    if (act == 0) {
                        C[idx] = v;
                    } else if (act == 1) {
                        C[idx] = v + bias[cc];
                    } else if (act == 5) {
                        float s = v + bias[cc];
                        s = s / (1.f + __expf(-s));
                        __nv_bfloat16 hh, ll;
                        split_bf16(s, hh, ll);
                        Csh[idx] = hh; Csl[idx] = ll;
                    } else { // 4 or 6
                        if (act == 6) v += bias[cc];
                        float rterm = mod ? v * gate[(long long)rr * N + cc]
                                          : v * (ls[cc] + 1.f);
                        C[idx] += rterm;
                    }
                }
            }
        }
    }

    __syncthreads();
    if (wid == 0)
        asm volatile("tcgen05.dealloc.cta_group::1.sync.aligned.b32 %0, %1;"
                     :: "r"(tmem_base), "r"(512u));

#else
    // ===================== mma.sync fallback (NT, two 128-col halves) ========
    __shared__ __align__(16) __nv_bfloat16 As[2][128][40];
    __shared__ __align__(16) __nv_bfloat16 Bs2[2][128][40];

    const int wr = wid & 3, wc = wid >> 2;
    const int lr = tid >> 1, lq = (tid & 1) * 8;

    for (int nh = 0; nh < 2; nh++) {
        int col0h = col0 + nh * 128;
        if (col0h >= N) break;

        auto load_stage = [&](int k0, int s) {
            int kg = k0 + lq;
            int abytes = (kg < lda) ? 16 : 0;
            const __nv_bfloat16* pah = abytes ? Ah + (size_t)(row0 + lr) * lda + kg : Ah;
            const __nv_bfloat16* pal = abytes ? Al + (size_t)(row0 + lr) * lda + kg : Al;
            CP_ASYNC16(smaddr(&As[s][lr][lq]),      pah, abytes);
            CP_ASYNC16(smaddr(&As[s][lr][16 + lq]), pal, abytes);
            int bbytes = ((col0h + lr) < N && kg < ldb) ? 16 : 0;
            const __nv_bfloat16* pbh = bbytes ? Bh + (size_t)(col0h + lr) * ldb + kg : Bh;
            const __nv_bfloat16* pbl = bbytes ? Bl + (size_t)(col0h + lr) * ldb + kg : Bl;
            CP_ASYNC16(smaddr(&Bs2[s][lr][lq]),      pbh, bbytes);
            CP_ASYNC16(smaddr(&Bs2[s][lr][16 + lq]), pbl, bbytes);
            CP_COMMIT();
        };

        float acc[2][8][4] = {};
        const int nk = (K + 15) >> 4;

        load_stage(0, 0);

        for (int t = 0; t < nk; t++) {
            int buf = t & 1;
            if (t + 1 < nk) { load_stage((t + 1) * 16, buf ^ 1); CP_WAIT1(); }
            else            { CP_WAIT0(); }
            __syncthreads();

            unsigned ah[2][4], al[2][4], bh[8][2], bl[8][2];
#pragma unroll
            for (int mt = 0; mt < 2; mt++) {
                int row = wr * 32 + mt * 16 + (lane & 15);
                int kk = (lane >> 4) * 8;
                ldsm4(ah[mt], smaddr(&As[buf][row][kk]));
                ldsm4(al[mt], smaddr(&As[buf][row][16 + kk]));
            }
#pragma unroll
            for (int ntp = 0; ntp < 4; ntp++) {
                int row = wc * 64 + ntp * 16 + (lane & 7) + ((lane >> 4) & 1) * 8;
                int col = ((lane >> 3) & 1) * 8;
                unsigned r4[4];
                ldsm4(r4, smaddr(&Bs2[buf][row][col]));
                bh[2*ntp][0] = r4[0]; bh[2*ntp][1] = r4[1];
                bh[2*ntp+1][0] = r4[2]; bh[2*ntp+1][1] = r4[3];
                ldsm4(r4, smaddr(&Bs2[buf][row][16 + col]));
                bl[2*ntp][0] = r4[0]; bl[2*ntp][1] = r4[1];
                bl[2*ntp+1][0] = r4[2]; bl[2*ntp+1][1] = r4[3];
            }
#pragma unroll
            for (int mt = 0; mt < 2; mt++)
#pragma unroll
                for (int nt = 0; nt < 8; nt++) {
                    mma16(acc[mt][nt], ah[mt], bh[nt]);
                    mma16(acc[mt][nt], ah[mt], bl[nt]);
                    mma16(acc[mt][nt], al[mt], bh[nt]);
                }
            __syncthreads();
        }

#pragma unroll
        for (int mt = 0; mt < 2; mt++) {
            int r = row0 + wr * 32 + mt * 16 + (lane >> 2);
#pragma unroll
            for (int nt = 0; nt < 8; nt++) {
                int c = col0h + wc * 64 + nt * 8 + ((lane & 3) << 1);
#pragma unroll
                for (int e = 0; e < 4; e++) {
                    int rr = r + ((e >> 1) << 3);
                    int cc = c + (e & 1);
                    if (rr >= M || cc >= N) continue;
                    float v = acc[mt][nt][e];
                    long long idx = (long long)rr * ldc + cc;
                    if (act == 0) {
                        C[idx] = v;
                    } else if (act == 1) {
                        C[idx] = v + bias[cc];
                    } else if (act == 5) {
                        float s = v + bias[cc];
                        s = s / (1.f + __expf(-s));
                        __nv_bfloat16 hh, ll;
                        split_bf16(s, hh, ll);
                        Csh[idx] = hh; Csl[idx] = ll;
                    } else if (act == 7) {
                        if (cc < 2048) {
                            mep.gb0[(long long)rr * 2048 + cc] = v + mep.bf0[cc];
                        } else if (cc < 3072) {
                            int c2 = cc - 2048;
                            mep.gt0[(long long)rr * 1024 + c2] =
                                1.f / (1.f + __expf(-(v + mep.ba0[c2])));
                        } else if (cc < 5120) {
                            int c2 = cc - 3072;
                            mep.gb1[(long long)rr * 2048 + c2] = v + mep.bf1[c2];
                        } else {
                            int c2 = cc - 5120;
                            mep.gt1[(long long)rr * 1024 + c2] =
                                1.f / (1.f + __expf(-(v + mep.ba1[c2])));
                        }
                    } else {
                        if (act == 6) v += bias[cc];
                        int bb = rr >> 11, nn = rr & (SEQ - 1);
                        int o0 = mp[bb*6+1], e0 = o0 + mp[bb*6+2];
                        int o1 = mp[bb*6+4], e1 = o1 + mp[bb*6+5];
                        bool mod = (nn >= o0 && nn < e0) || (nn >= o1 && nn < e1);
                        float rterm = mod ? v * gate[(long long)rr * N + cc]
                                          : v * (ls[cc] + 1.f);
                        C[idx] += rterm;
                    }
                }
            }
        }
        __syncthreads();
    }
#endif
}

// ---------------------------------------------------------------------------
// Flash attention on pre-split qkv planes (mma.sync; ~5% of MACs).
// ---------------------------------------------------------------------------
__global__ __launch_bounds__(256, 1)
void flash_kernel(const int* __restrict__ mp)
{
    __shared__ __align__(16) __nv_bfloat16 K2[64][136];
    __shared__ __align__(16) __nv_bfloat16 V2[64][136];

    const int tid = threadIdx.x;
    const int lane = tid & 31, w = tid >> 5;
    const int z = blockIdx.y, b = z >> 4, h = z & 15;
    const int i0 = blockIdx.x * 128;

    const __nv_bfloat16* qh_p = g_qkvh + (long long)b * SEQ * 3072 + h * 64;
    const __nv_bfloat16* ql_p = g_qkvl + (long long)b * SEQ * 3072 + h * 64;

    const int off0 = mp[b*6+1], end0 = off0 + mp[b*6+2];
    const int off1 = mp[b*6+4], end1 = off1 + mp[b*6+5];

    unsigned qh[4][4], ql[4][4];
#pragma unroll
    for (int half = 0; half < 2; half++) {
#pragma unroll
        for (int p = 0; p < 2; p++) {
            int f = p * 256 + tid;
            int r = f >> 3, s = (f & 7) * 8;
            long long rowoff = (long long)(i0 + half * 64 + r) * 3072 + s;
            *(uint4*)&K2[r][s]      = *(const uint4*)(qh_p + rowoff);
            *(uint4*)&K2[r][64 + s] = *(const uint4*)(ql_p + rowoff);
        }
        __syncthreads();
        if ((w >> 2) == half) {
            int rl = (w & 3) * 16 + (lane & 15);
#pragma unroll
            for (int ks = 0; ks < 4; ks++) {
                int kk = ks * 16 + (lane >> 4) * 8;
                ldsm4(qh[ks], smaddr(&K2[rl][kk]));
                ldsm4(ql[ks], smaddr(&K2[rl][64 + kk]));
            }
        }
        __syncthreads();
    }

    float Oacc[8][4] = {};
    float m0 = MASKVAL, m1 = MASKVAL;
    float l0 = 0.f, l1 = 0.f;

    const int irow0 = i0 + w * 16 + (lane >> 2);
    const int irow1 = irow0 + 8;
    const bool rf00 = irow0 >= off0, rf01 = irow0 >= off1;
    const bool rf10 = irow1 >= off0, rf11 = irow1 >= off1;

    const __nv_bfloat16* kh_p = qh_p + 1024;
    const __nv_bfloat16* kl_p = ql_p + 1024;
    const __nv_bfloat16* vh_p = qh_p + 2048;
    const __nv_bfloat16* vl_p = ql_p + 2048;

    for (int jt = 0; jt < 32; jt++) {
        int j0 = jt * 64;
        bool causal_p = (j0 <= i0 + 127);
        bool mod_p = ((i0 + 127 >= off0) && (j0 < end0)) ||
                     ((i0 + 127 >= off1) && (j0 < end1));
        if (!(causal_p || mod_p)) continue;

#pragma unroll
        for (int p = 0; p < 2; p++) {
            int f = p * 256 + tid;
            int r = f >> 3, s = (f & 7) * 8;
            long long rowoff = (long long)(j0 + r) * 3072 + s;
            CP_ASYNC16(smaddr(&K2[r][s]),      kh_p + rowoff, 16);
            CP_ASYNC16(smaddr(&K2[r][64 + s]), kl_p + rowoff, 16);
            CP_ASYNC16(smaddr(&V2[r][s]),      vh_p + rowoff, 16);
            CP_ASYNC16(smaddr(&V2[r][64 + s]), vl_p + rowoff, 16);
        }
        CP_COMMIT();
        CP_WAIT0();
        __syncthreads();

        float S[8][4] = {};
#pragma unroll
        for (int ks = 0; ks < 4; ks++) {
            unsigned kh_f[8][2], kl_f[8][2];
#pragma unroll
            for (int ntp = 0; ntp < 4; ntp++) {
                int row = ntp * 16 + (lane & 7) + ((lane >> 4) & 1) * 8;
                int col = ks * 16 + ((lane >> 3) & 1) * 8;
                unsigned r4[4];
                ldsm4(r4, smaddr(&K2[row][col]));
                kh_f[2*ntp][0] = r4[0]; kh_f[2*ntp][1] = r4[1];
                kh_f[2*ntp+1][0] = r4[2]; kh_f[2*ntp+1][1] = r4[3];
                ldsm4(r4, smaddr(&K2[row][64 + col]));
                kl_f[2*ntp][0] = r4[0]; kl_f[2*ntp][1] = r4[1];
                kl_f[2*ntp+1][0] = r4[2]; kl_f[2*ntp+1][1] = r4[3];
            }
#pragma unroll
            for (int nt = 0; nt < 8; nt++) {
                mma16(S[nt], qh[ks], kh_f[nt]);
                mma16(S[nt], qh[ks], kl_f[nt]);
                mma16(S[nt], ql[ks], kh_f[nt]);
            }
        }

        float mt0 = MASKVAL, mt1 = MASKVAL;
#pragma unroll
        for (int nt = 0; nt < 8; nt++) {
            int jc = j0 + nt * 8 + ((lane & 3) << 1);
#pragma unroll
            for (int e = 0; e < 4; e++) {
                int jj = jc + (e & 1);
                float s = softcap_tanh(S[nt][e]);
                bool keep;
                if (e < 2) keep = (irow0 >= jj) || (rf00 && jj < end0) || (rf01 && jj < end1);
                else       keep = (irow1 >= jj) || (rf10 && jj < end0) || (rf11 && jj < end1);
                s = keep ? s : MASKVAL;
                S[nt][e] = s;
                if (e < 2) mt0 = fmaxf(mt0, s); else mt1 = fmaxf(mt1, s);
            }
        }
        mt0 = fmaxf(mt0, __shfl_xor_sync(0xffffffffu, mt0, 1));
        mt0 = fmaxf(mt0, __shfl_xor_sync(0xffffffffu, mt0, 2));
        mt1 = fmaxf(mt1, __shfl_xor_sync(0xffffffffu, mt1, 1));
        mt1 = fmaxf(mt1, __shfl_xor_sync(0xffffffffu, mt1, 2));

        float mn0 = fmaxf(m0, mt0), mn1 = fmaxf(m1, mt1);
        float a0 = __expf(m0 - mn0), a1 = __expf(m1 - mn1);
        m0 = mn0; m1 = mn1;
        l0 *= a0; l1 *= a1;
#pragma unroll
        for (int nt = 0; nt < 8; nt++) {
            Oacc[nt][0] *= a0; Oacc[nt][1] *= a0;
            Oacc[nt][2] *= a1; Oacc[nt][3] *= a1;
        }

        unsigned ph_[4][4], pl_[4][4];
#pragma unroll
        for (int kt = 0; kt < 4; kt++) {
#pragma unroll
            for (int half = 0; half < 2; half++) {
                int nt = 2 * kt + half;
                float p0 = __expf(S[nt][0] - mn0);
                float p1 = __expf(S[nt][1] - mn0);
                float p2 = __expf(S[nt][2] - mn1);
                float p3 = __expf(S[nt][3] - mn1);
                l0 += p0 + p1; l1 += p2 + p3;
                __nv_bfloat16 h0,lo0,h1,lo1,h2,lo2,h3,lo3;
                split_bf16(p0, h0, lo0); split_bf16(p1, h1, lo1);
                split_bf16(p2, h2, lo2); split_bf16(p3, h3, lo3);
                ph_[kt][half*2+0] = pk2(h0, h1);
                ph_[kt][half*2+1] = pk2(h2, h3);
                pl_[kt][half*2+0] = pk2(lo0, lo1);
                pl_[kt][half*2+1] = pk2(lo2, lo3);
            }
        }

#pragma unroll
        for (int kt = 0; kt < 4; kt++) {
            unsigned vh_f[8][2], vl_f[8][2];
#pragma unroll
            for (int ntp = 0; ntp < 4; ntp++) {
                int row = kt * 16 + (lane & 15);
                int col = ntp * 16 + (lane >> 4) * 8;
                unsigned r4[4];
                ldsm4t(r4, smaddr(&V2[row][col]));
                vh_f[2*ntp][0] = r4[0]; vh_f[2*ntp][1] = r4[1];
                vh_f[2*ntp+1][0] = r4[2]; vh_f[2*ntp+1][1] = r4[3];
                ldsm4t(r4, smaddr(&V2[row][64 + col]));
                vl_f[2*ntp][0] = r4[0]; vl_f[2*ntp][1] = r4[1];
                vl_f[2*ntp+1][0] = r4[2]; vl_f[2*ntp+1][1] = r4[3];
            }
#pragma unroll
            for (int nt = 0; nt < 8; nt++) {
                mma16(Oacc[nt], ph_[kt], vh_f[nt]);
                mma16(Oacc[nt], ph_[kt], vl_f[nt]);
                mma16(Oacc[nt], pl_[kt], vh_f[nt]);
            }
        }
        __syncthreads();
    }

    float ls0 = l0 + __shfl_xor_sync(0xffffffffu, l0, 1);
    ls0 += __shfl_xor_sync(0xffffffffu, ls0, 2);
    float ls1 = l1 + __shfl_xor_sync(0xffffffffu, l1, 1);
    ls1 += __shfl_xor_sync(0xffffffffu, ls1, 2);
    float inv0 = 1.f / ls0, inv1 = 1.f / ls1;

    __nv_bfloat16* ohp = g_oh + (long long)b * SEQ * DIM + h * 64;
    __nv_bfloat16* olp = g_ol + (long long)b * SEQ * DIM + h * 64;
#pragma unroll
    for (int nt = 0; nt < 8; nt++) {
        int d = nt * 8 + ((lane & 3) << 1);
        float v00 = Oacc[nt][0] * inv0, v01 = Oacc[nt][1] * inv0;
        float v10 = Oacc[nt][2] * inv1, v11 = Oacc[nt][3] * inv1;
        __nv_bfloat16 hh, ll;
        split_bf16(v00, hh, ll);
        ohp[(long long)irow0 * DIM + d] = hh;     olp[(long long)irow0 * DIM + d] = ll;
        split_bf16(v01, hh, ll);
        ohp[(long long)irow0 * DIM + d + 1] = hh; olp[(long long)irow0 * DIM + d + 1] = ll;
        split_bf16(v10, hh, ll);
        ohp[(long long)irow1 * DIM + d] = hh;     olp[(long long)irow1 * DIM + d] = ll;
        split_bf16(v11, hh, ll);
        ohp[(long long)irow1 * DIM + d + 1] = hh; olp[(long long)irow1 * DIM + d + 1] = ll;
    }
}

// ---------------------------------------------------------------------------
// Fourier features -> split planes (zero pad cols >= 1025)
// ---------------------------------------------------------------------------
__global__ void fourier_kernel(const float* __restrict__ times,
                               const float* __restrict__ fw)
{
    long long idx = (long long)blockIdx.x * blockDim.x + threadIdx.x;
    if (idx >= (long long)TOK * FOURIER_LD) return;
    int t = (int)(idx / FOURIER_LD);
    int c = (int)(idx % FOURIER_LD);
    float out = 0.f;
    if (c == 0)         out = times[t];
    else if (c <= 512)  out = __sinf(times[t] * fw[c - 1] * TWO_PI);
    else if (c <= 1024) out = __cosf(times[t] * fw[c - 513] * TWO_PI);
    __nv_bfloat16 h, l;
    split_bf16(out, h, l);
    g_fh[idx] = h; g_fl[idx] = l;
}

// ---------------------------------------------------------------------------
// Fused LN -> adaptive modulation -> RMSnorm -> split h planes
// ---------------------------------------------------------------------------
__global__ void prenorm_kernel(const float* __restrict__ lng,
                               const float* __restrict__ rg,
                               const int* __restrict__ mp,
                               const float* __restrict__ gb)
{
    __shared__ float sm[8];
    int tok = blockIdx.x;
    int b = tok >> 11, n = tok & (SEQ - 1);
    bool mod = false;
#pragma unroll
    for (int m = 0; m < 2; m++) {
        int off = mp[b * 6 + m * 3 + 1];
        int len = mp[b * 6 + m * 3 + 2];
        if (n >= off && n < off + len) mod = true;
    }
    const float* xr = g_x + (long long)tok * DIM;
    int tid = threadIdx.x;

    float v[4];
    float s = 0.f, ss = 0.f;
#pragma unroll
    for (int i = 0; i < 4; i++) {
        float f = xr[tid + i * 256];
        v[i] = f; s += f; ss += f * f;
    }
    float mean = block_reduce_sum(s, sm) * (1.f / DIM);
    float ex2  = block_reduce_sum(ss, sm) * (1.f / DIM);
    float inv  = rsqrtf(ex2 - mean * mean + 1e-5f);

    const float* gbr = gb + (long long)tok * 2 * DIM;
    float hv[4];
    float ss2 = 0.f;
#pragma unroll
    for (int i = 0; i < 4; i++) {
        int c = tid + i * 256;
        float ln = (v[i] - mean) * inv;
        float hh;
        if (mod) hh = ln * (gbr[c] + 1.f) + gbr[DIM + c];
        else     hh = ln * (lng[c] + 1.f);
        hv[i] = hh; ss2 += hh * hh;
    }
    float nrm = sqrtf(block_reduce_sum(ss2, sm));
    float scale = 32.f / fmaxf(nrm, 1e-12f);
#pragma unroll
    for (int i = 0; i < 4; i++) {
        int c = tid + i * 256;
        float val = hv[i] * scale * (rg[c] + 1.f);
        __nv_bfloat16 hh, ll;
        split_bf16(val, hh, ll);
        g_hh[(long long)tok * DIM + c] = hh;
        g_hl[(long long)tok * DIM + c] = ll;
    }
}

// ---------------------------------------------------------------------------
// Rotary (q,k; q scaled) + pass-through v, all -> split qkv planes
// ---------------------------------------------------------------------------
__global__ void rotary_split_kernel(const float* __restrict__ rot)
{
    int tok = blockIdx.x;
    int n = tok & (SEQ - 1);
#pragma unroll
    for (int g = 0; g < 6; g++) {
        int p = threadIdx.x + g * 256;
        int which = p / 512;
        int rem = p & 511;
        int head = rem >> 5;
        int pr = rem & 31;
        long long base = (long long)tok * 3072 + which * 1024 + head * 64 + pr * 2;
        float e = g_qkv[base], o = g_qkv[base + 1];
        if (which < 2) {
            float th = rot[n * 64 + pr * 2];
            float c = cosf(th), s = sinf(th);
            float ne = e * c - o * s;
            float no = o * c + e * s;
            if (which == 0) { ne *= QK_SCALE; no *= QK_SCALE; }
            e = ne; o = no;
        }
        __nv_bfloat16 hh, ll;
        split_bf16(e, hh, ll);
        g_qkvh[base] = hh; g_qkvl[base] = ll;
        split_bf16(o, hh, ll);
        g_qkvh[base + 1] = hh; g_qkvl[base + 1] = ll;
    }
}

// ---------------------------------------------------------------------------
// GEGLU -> split act planes (zero pad cols >= 2730)
// ---------------------------------------------------------------------------
__global__ void geglu_kernel()
{
    long long idx = (long long)blockIdx.x * blockDim.x + threadIdx.x;
    if (idx >= (long long)TOK * ACT_LD) return;
    int t = (int)(idx / ACT_LD);
    int c = (int)(idx % ACT_LD);
    float v = 0.f;
    if (c < DFF) {
        const float* row = g_ff1 + (long long)t * 2 * DFF;
        float u = row[c];
        float gg = row[DFF + c];
        float ge = 0.5f * gg * (1.f + erff(gg * 0.70710678118654752f));
        v = ge * u;
    }
    __nv_bfloat16 hh, ll;
    split_bf16(v, hh, ll);
    g_acth[idx] = hh; g_actl[idx] = ll;
}

// ---------------------------------------------------------------------------
// Final rmsnorm -> d_out
// ---------------------------------------------------------------------------
__global__ void final_rms_kernel(const float* __restrict__ fg,
                                 float* __restrict__ out)
{
    __shared__ float sm[8];
    int tok = blockIdx.x;
    const float* xr = g_x + (long long)tok * DIM;
    int tid = threadIdx.x;
    float v[4];
    float ss = 0.f;
#pragma unroll
    for (int i = 0; i < 4; i++) {
        v[i] = xr[tid + i * 256];
        ss += v[i] * v[i];
    }
    float nrm = sqrtf(block_reduce_sum(ss, sm));
    float scale = 32.f / fmaxf(nrm, 1e-12f);
    float* o = out + (long long)tok * DIM;
#pragma unroll
    for (int i = 0; i < 4; i++) {
        int c = tid + i * 256;
        o[c] = v[i] * scale * (fg[c] + 1.f);
    }
}

// ---------------------------------------------------------------------------
// Host side
// ---------------------------------------------------------------------------
#define TC5_DSMEM 197632u

static void launch_gemm_tc5(const __nv_bfloat16* Ah, const __nv_bfloat16* Al, int lda,
                            const __nv_bfloat16* Bh, const __nv_bfloat16* Bl, int ldb,
                            const float* bias, float* C, int ldc,
                            __nv_bfloat16* Csh, __nv_bfloat16* Csl,
                            int M, int N, int K, int act,
                            const int* skmp = nullptr,
                            const float* gate = nullptr, const float* ls = nullptr,
                            const int* mp = nullptr,
                            const MergedEp* mepp = nullptr)
{
    MergedEp mep = {};
    if (mepp) mep = *mepp;
    dim3 grid((N + 255) / 256, (M + 127) / 128, 1);
    gemm_tc5_kernel<<<grid, 256, TC5_DSMEM>>>(Ah, Al, lda, Bh, Bl, ldb, bias, C, ldc,
                                              Csh, Csl, M, N, K, act, skmp, gate, ls,
                                              mp, mep);
}

extern "C" void kernel_launch(void* const* d_in, const int* in_sizes, int n_in,
                              void* d_out, int out_size)
{
    const float* in_x        = (const float*)d_in[0];
    const float* in_times    = (const float*)d_in[1];
    const float* in_rot      = (const float*)d_in[2];
    const float* in_fw       = (const float*)d_in[3];
    const float* in_time_w   = (const float*)d_in[4];
    const float* in_time_b   = (const float*)d_in[5];
    const float* a_film_w    = (const float*)d_in[6];
    const float* a_film_b    = (const float*)d_in[7];
    const float* a_az_w      = (const float*)d_in[8];
    const float* a_az_b      = (const float*)d_in[9];
    const float* a_ln_g      = (const float*)d_in[10];
    const float* a_ls        = (const float*)d_in[11];
    const float* a_rms_g     = (const float*)d_in[12];
    const float* w_qkv       = (const float*)d_in[13];
    const float* w_out       = (const float*)d_in[14];
    const float* f_film_w    = (const float*)d_in[15];
    const float* f_film_b    = (const float*)d_in[16];
    const float* f_az_w      = (const float*)d_in[17];
    const float* f_az_b      = (const float*)d_in[18];
    const float* f_ln_g      = (const float*)d_in[19];
    const float* f_ls        = (const float*)d_in[20];
    const float* f_rms_g     = (const float*)d_in[21];
    const float* ff_w1       = (const float*)d_in[22];
    const float* ff_b1       = (const float*)d_in[23];
    const float* ff_w2       = (const float*)d_in[24];
    const float* ff_b2       = (const float*)d_in[25];
    const float* final_g     = (const float*)d_in[26];
    const int*   mod_pos     = (const int*)d_in[27];

    cudaFuncSetAttribute(gemm_tc5_kernel,
                         cudaFuncAttributeMaxDynamicSharedMemorySize, TC5_DSMEM);

    float *p_qkv, *p_gba, *p_gbf, *p_gatea, *p_gatef, *p_ff1, *p_x;
    __nv_bfloat16 *p_fh, *p_fl, *p_condh, *p_condl, *p_hh, *p_hl,
                  *p_qkvh, *p_qkvl, *p_oh, *p_ol, *p_acth, *p_actl,
                  *p_wh, *p_wl;
    cudaGetSymbolAddress((void**)&p_qkv,   g_qkv);
    cudaGetSymbolAddress((void**)&p_gba,   g_gba);
    cudaGetSymbolAddress((void**)&p_gbf,   g_gbf);
    cudaGetSymbolAddress((void**)&p_gatea, g_gatea);
    cudaGetSymbolAddress((void**)&p_gatef, g_gatef);
    cudaGetSymbolAddress((void**)&p_ff1,   g_ff1);
    cudaGetSymbolAddress((void**)&p_x,     g_x);
    cudaGetSymbolAddress((void**)&p_fh,    g_fh);
    cudaGetSymbolAddress((void**)&p_fl,    g_fl);
    cudaGetSymbolAddress((void**)&p_condh, g_condh);
    cudaGetSymbolAddress((void**)&p_condl, g_condl);
    cudaGetSymbolAddress((void**)&p_hh,    g_hh);
    cudaGetSymbolAddress((void**)&p_hl,    g_hl);
    cudaGetSymbolAddress((void**)&p_qkvh,  g_qkvh);
    cudaGetSymbolAddress((void**)&p_qkvl,  g_qkvl);
    cudaGetSymbolAddress((void**)&p_oh,    g_oh);
    cudaGetSymbolAddress((void**)&p_ol,    g_ol);
    cudaGetSymbolAddress((void**)&p_acth,  g_acth);
    cudaGetSymbolAddress((void**)&p_actl,  g_actl);
    cudaGetSymbolAddress((void**)&p_wh,    g_wh);
    cudaGetSymbolAddress((void**)&p_wl,    g_wl);

    cudaMemcpyAsync(p_x, in_x, (size_t)TOK * DIM * sizeof(float),
                    cudaMemcpyDeviceToDevice, 0);

    // ------------- weight split + transpose: W[R=K,C=N] -> WT[N,Kpad] -------------
    long long wo = 0;
    auto wregT = [&](const float* src, int R, int C, int Rpad) -> long long {
        long long o = wo;
        dim3 grid((C + 63) / 64, (Rpad + 63) / 64);
        wsplitT_kernel<<<grid, 256>>>(src, p_wh + o, p_wl + o, R, C, Rpad);
        wo += (long long)C * Rpad;
        return o;
    };
    long long o_timew = wregT(in_time_w, 1025, DCOND, FOURIER_LD);
    long long o_condw[2], o_qkvw[2], o_woutw[2], o_ff1w[2], o_ff2w[2];
    for (int l = 0; l < DEPTH; l++) {
        // merged cond weights: [film_a(2048) | az_a(1024) | film_f(2048) | az_f(1024)]
        o_condw[l] = wregT(a_film_w + (long long)l * DCOND * 2 * DIM, DCOND, 2 * DIM, DCOND);
        wregT(a_az_w   + (long long)l * DCOND * DIM,     DCOND, DIM, DCOND);
        wregT(f_film_w + (long long)l * DCOND * 2 * DIM, DCOND, 2 * DIM, DCOND);
        wregT(f_az_w   + (long long)l * DCOND * DIM,     DCOND, DIM, DCOND);
        o_qkvw[l]  = wregT(w_qkv    + (long long)l * DIM * 3 * DIM,   DIM, 3 * DIM, DIM);
        o_woutw[l] = wregT(w_out    + (long long)l * DIM * DIM,       DIM, DIM, DIM);
        o_ff1w[l]  = wregT(ff_w1    + (long long)l * DIM * 2 * DFF,   DIM, 2 * DFF, DIM);
        o_ff2w[l]  = wregT(ff_w2    + (long long)l * DFF * DIM,       DFF, DIM, ACT_LD);
    }

    // ------------- time conditioning -------------
    {
        long long tot = (long long)TOK * FOURIER_LD;
        fourier_kernel<<<(unsigned)((tot + 255) / 256), 256>>>(in_times, in_fw);
        launch_gemm_tc5(p_fh, p_fl, FOURIER_LD,
                        p_wh + o_timew, p_wl + o_timew, FOURIER_LD,
                        in_time_b, nullptr, DCOND,
                        p_condh, p_condl,
                        TOK, DCOND, 1025, /*silu->split*/5);
    }

    for (int l = 0; l < DEPTH; l++) {
        const float* lnG[2]   = { a_ln_g + (long long)l * DIM,
                                  f_ln_g + (long long)l * DIM };
        const float* lsP[2]   = { a_ls + (long long)l * DIM,
                                  f_ls + (long long)l * DIM };
        const float* rmsG[2]  = { a_rms_g + (long long)l * DIM,
                                  f_rms_g + (long long)l * DIM };

        // ======== merged cond GEMM: film_a | az_a | film_f | az_f ========
        MergedEp mep;
        mep.bf0 = a_film_b + (long long)l * 2 * DIM;
        mep.ba0 = a_az_b   + (long long)l * DIM;
        mep.bf1 = f_film_b + (long long)l * 2 * DIM;
        mep.ba1 = f_az_b   + (long long)l * DIM;
        mep.gb0 = p_gba;  mep.gt0 = p_gatea;
        mep.gb1 = p_gbf;  mep.gt1 = p_gatef;
        launch_gemm_tc5(p_condh, p_condl, DCOND,
                        p_wh + o_condw[l], p_wl + o_condw[l], DCOND,
                        nullptr, nullptr, 0, nullptr, nullptr,
                        TOK, 6 * DIM, DCOND, /*merged*/7, mod_pos,
                        nullptr, nullptr, nullptr, &mep);

        // ================= attention block =================
        prenorm_kernel<<<TOK, 256>>>(lnG[0], rmsG[0], mod_pos, p_gba);

        launch_gemm_tc5(p_hh, p_hl, DIM,
                        p_wh + o_qkvw[l], p_wl + o_qkvw[l], DIM,
                        nullptr, p_qkv, 3 * DIM, nullptr, nullptr,
                        TOK, 3 * DIM, DIM, 0);
        rotary_split_kernel<<<TOK, 256>>>(in_rot);

        {
            dim3 fg(SEQ / 128, BATCH * HEADS);
            flash_kernel<<<fg, 256>>>(mod_pos);
        }

        // wout with fused gated residual into g_x
        launch_gemm_tc5(p_oh, p_ol, DIM,
                        p_wh + o_woutw[l], p_wl + o_woutw[l], DIM,
                        nullptr, p_x, DIM, nullptr, nullptr,
                        TOK, DIM, DIM, 4, nullptr, p_gatea, lsP[0], mod_pos);

        // ================= feed-forward block =================
        prenorm_kernel<<<TOK, 256>>>(lnG[1], rmsG[1], mod_pos, p_gbf);

        launch_gemm_tc5(p_hh, p_hl, DIM,
                        p_wh + o_ff1w[l], p_wl + o_ff1w[l], DIM,
                        ff_b1 + (long long)l * 2 * DFF, p_ff1, 2 * DFF,
                        nullptr, nullptr,
                        TOK, 2 * DFF, DIM, 1);
        {
            long long tot = (long long)TOK * ACT_LD;
            geglu_kernel<<<(unsigned)((tot + 255) / 256), 256>>>();
        }

        // ff2 with bias + fused gated residual into g_x
        launch_gemm_tc5(p_acth, p_actl, ACT_LD,
                        p_wh + o_ff2w[l], p_wl + o_ff2w[l], ACT_LD,
                        ff_b2 + (long long)l * DIM, p_x, DIM, nullptr, nullptr,
                        TOK, DIM, DFF, 6, nullptr, p_gatef, lsP[1], mod_pos);
    }

    final_rms_kernel<<<TOK, 256>>>(final_g, (float*)d_out);

    (void)in_sizes; (void)n_in; (void)out_size;
}